// round 3
// baseline (speedup 1.0000x reference)
#include <cuda_runtime.h>
#include <cuda_fp16.h>

// ---------------- problem-size constants ----------------
#define NMAX 50000
#define EMAX 1600000

// ---------------- scratch (device globals: no allocation allowed) --------
__device__ int   g_deg[NMAX];
__device__ float g_dinv[NMAX];
__device__ int   g_rowptr[NMAX + 1];
__device__ int   g_cursor[NMAX];
__device__ int2  g_cw[EMAX];                       // packed (src, w-bits)
__device__ __align__(16) __half g_h[(size_t)NMAX * 128];   // fp16 gather operand
__device__ __align__(16) float  g_a[(size_t)NMAX * 128];   // fp32 layer-1 output
__device__ int g_bsum[64];
__device__ int g_boff[64];
__device__ int g_is64;   // 1 if edge_index is int64, 0 if int32

// ---------------- packed fp32x2 helpers (Blackwell FFMA2) ----------------
__device__ __forceinline__ unsigned long long pack2(float lo, float hi) {
    unsigned long long r;
    asm("mov.b64 %0, {%1, %2};"
        : "=l"(r) : "r"(__float_as_uint(lo)), "r"(__float_as_uint(hi)));
    return r;
}
__device__ __forceinline__ void unpack2(unsigned long long v, float &lo, float &hi) {
    unsigned int a, b;
    asm("mov.b64 {%0, %1}, %2;" : "=r"(a), "=r"(b) : "l"(v));
    lo = __uint_as_float(a);
    hi = __uint_as_float(b);
}
__device__ __forceinline__ void ffma2(unsigned long long &d,
                                      unsigned long long a,
                                      unsigned long long b) {
    asm("fma.rn.f32x2 %0, %1, %2, %0;" : "+l"(d) : "l"(a), "l"(b));
}

// ---------------- edge-index width detection ----------------
__global__ void detect_width_kernel(const unsigned int* __restrict__ p) {
    __shared__ int any;
    if (threadIdx.x == 0) any = 0;
    __syncthreads();
    for (int i = threadIdx.x; i < 2048; i += blockDim.x) {
        if (p[2 * i + 1] != 0u) any = 1;
    }
    __syncthreads();
    if (threadIdx.x == 0) g_is64 = any ? 0 : 1;
}

// ---------------- degree / normalization ----------------
__global__ void zero_deg_kernel(int n) {
    int i = blockIdx.x * blockDim.x + threadIdx.x;
    if (i < n) g_deg[i] = 0;
}

// dst-only degree count, 2 edges per thread (vectorized)
__global__ void count_deg_kernel(const void* __restrict__ ei, int e_total) {
    int t = blockIdx.x * blockDim.x + threadIdx.x;
    int base = t * 2;
    if (base >= e_total) return;
    int d0, d1;
    bool two = (base + 1 < e_total);
    if (g_is64) {
        const long long* p = (const long long*)ei + e_total;   // dst half
        if (two) {
            longlong2 v = *reinterpret_cast<const longlong2*>(p + base);
            d0 = (int)v.x; d1 = (int)v.y;
        } else { d0 = (int)p[base]; d1 = -1; }
    } else {
        const int* p = (const int*)ei + e_total;
        if (two) {
            int2 v = *reinterpret_cast<const int2*>(p + base);
            d0 = v.x; d1 = v.y;
        } else { d0 = p[base]; d1 = -1; }
    }
    atomicAdd(&g_deg[d0], 1);
    if (two) atomicAdd(&g_deg[d1], 1);
}

__global__ void dinv_kernel(int n) {
    int i = blockIdx.x * blockDim.x + threadIdx.x;
    if (i < n) g_dinv[i] = rsqrtf((float)(g_deg[i] + 1));  // +1 self loop
}

// ---------------- 3-kernel exclusive scan of g_deg -> g_rowptr -----------
__global__ void scan_part_kernel(int n) {
    __shared__ int sm[1024];
    int i = blockIdx.x * 1024 + threadIdx.x;
    sm[threadIdx.x] = (i < n) ? g_deg[i] : 0;
    __syncthreads();
    for (int s = 512; s > 0; s >>= 1) {
        if (threadIdx.x < s) sm[threadIdx.x] += sm[threadIdx.x + s];
        __syncthreads();
    }
    if (threadIdx.x == 0) g_bsum[blockIdx.x] = sm[0];
}

__global__ void scan_top_kernel(int nblocks) {
    if (threadIdx.x == 0 && blockIdx.x == 0) {
        int run = 0;
        for (int b = 0; b < nblocks; b++) {
            g_boff[b] = run;
            run += g_bsum[b];
        }
    }
}

__global__ void scan_final_kernel(int n) {
    __shared__ int sm[1024];
    int tid = threadIdx.x;
    int i = blockIdx.x * 1024 + tid;
    int v = (i < n) ? g_deg[i] : 0;
    sm[tid] = v;
    __syncthreads();
    for (int off = 1; off < 1024; off <<= 1) {
        int t = (tid >= off) ? sm[tid - off] : 0;
        __syncthreads();
        sm[tid] += t;
        __syncthreads();
    }
    if (i < n) {
        int start = g_boff[blockIdx.x] + sm[tid] - v;   // exclusive
        g_rowptr[i] = start;
        g_cursor[i] = start;
        if (i == n - 1) g_rowptr[n] = start + v;
    }
}

// ---------------- CSC build (dst-sorted edges), 2 edges per thread -------
__global__ void build_csr_kernel(const void* __restrict__ ei, int e_total) {
    int t = blockIdx.x * blockDim.x + threadIdx.x;
    int base = t * 2;
    if (base >= e_total) return;
    int s0, d0, s1 = 0, d1 = 0;
    bool two = (base + 1 < e_total);
    if (g_is64) {
        const long long* ps = (const long long*)ei;
        const long long* pd = ps + e_total;
        if (two) {
            longlong2 sv = *reinterpret_cast<const longlong2*>(ps + base);
            longlong2 dv = *reinterpret_cast<const longlong2*>(pd + base);
            s0 = (int)sv.x; s1 = (int)sv.y;
            d0 = (int)dv.x; d1 = (int)dv.y;
        } else { s0 = (int)ps[base]; d0 = (int)pd[base]; }
    } else {
        const int* ps = (const int*)ei;
        const int* pd = ps + e_total;
        if (two) {
            int2 sv = *reinterpret_cast<const int2*>(ps + base);
            int2 dv = *reinterpret_cast<const int2*>(pd + base);
            s0 = sv.x; s1 = sv.y;
            d0 = dv.x; d1 = dv.y;
        } else { s0 = ps[base]; d0 = pd[base]; }
    }
    {
        int pos = atomicAdd(&g_cursor[d0], 1);
        float w = g_dinv[s0] * g_dinv[d0];
        g_cw[pos] = make_int2(s0, __float_as_int(w));
    }
    if (two) {
        int pos = atomicAdd(&g_cursor[d1], 1);
        float w = g_dinv[s1] * g_dinv[d1];
        g_cw[pos] = make_int2(s1, __float_as_int(w));
    }
}

// ---------------- GEMM: C[M,128] = A[M,128] @ W[128,128] -> fp16 ---------
// Block: 64 rows x 128 cols, 256 threads, each thread 4 rows x 4 col-pairs.
__global__ void __launch_bounds__(256) gemm128_kernel(
    const float* __restrict__ A, const float* __restrict__ W,
    __half* __restrict__ C, int M)
{
    __shared__ unsigned long long xs[64][33];   // packed (v, v), padded
    __shared__ unsigned long long ws[32][64];   // packed (W[k][2cp], W[k][2cp+1])

    int tid  = threadIdx.x;
    int row0 = blockIdx.x * 64;
    int cpg  = tid & 15;        // col-pair group: cp = 16*j + cpg
    int rg   = tid >> 4;        // row group: rows rg*4 + i

    unsigned long long acc[4][4];
#pragma unroll
    for (int i = 0; i < 4; i++)
#pragma unroll
        for (int j = 0; j < 4; j++) acc[i][j] = 0ull;

    for (int kb = 0; kb < 128; kb += 32) {
        {
            int lr = tid >> 5;
            int lk = tid & 31;
#pragma unroll
            for (int p = 0; p < 8; p++) {
                int r = lr + p * 8;
                int grow = row0 + r;
                float v = (grow < M) ? A[(size_t)grow * 128 + kb + lk] : 0.f;
                xs[r][lk] = pack2(v, v);
            }
        }
        {
#pragma unroll
            for (int p = 0; p < 8; p++) {
                int idx = p * 256 + tid;
                int kk = idx >> 6;
                int cp = idx & 63;
                float2 wv = *reinterpret_cast<const float2*>(&W[(kb + kk) * 128 + cp * 2]);
                ws[kk][cp] = pack2(wv.x, wv.y);
            }
        }
        __syncthreads();

#pragma unroll
        for (int kk = 0; kk < 32; kk++) {
            unsigned long long wv[4], xv[4];
#pragma unroll
            for (int j = 0; j < 4; j++) wv[j] = ws[kk][16 * j + cpg];
#pragma unroll
            for (int i = 0; i < 4; i++) xv[i] = xs[rg * 4 + i][kk];
#pragma unroll
            for (int i = 0; i < 4; i++)
#pragma unroll
                for (int j = 0; j < 4; j++) ffma2(acc[i][j], xv[i], wv[j]);
        }
        __syncthreads();
    }

#pragma unroll
    for (int i = 0; i < 4; i++) {
        int grow = row0 + rg * 4 + i;
        if (grow < M) {
#pragma unroll
            for (int j = 0; j < 4; j++) {
                int cp = 16 * j + cpg;
                float lo, hi;
                unpack2(acc[i][j], lo, hi);
                *reinterpret_cast<__half2*>(&C[(size_t)grow * 128 + cp * 2]) =
                    __floats2half2_rn(lo, hi);
            }
        }
    }
}

// ---------------- aggregation layer 1: a = relu(b + dinv^2*h[i] + sum w*h[src])
// One warp per node; lane handles 4 cols (8 bytes fp16).
__global__ void __launch_bounds__(256) aggregate1_kernel(
    const uint2* __restrict__ h2, const float* __restrict__ bias,
    float4* __restrict__ out4, int n)
{
    int warp = (blockIdx.x * blockDim.x + threadIdx.x) >> 5;
    int lane = threadIdx.x & 31;
    if (warp >= n) return;
    int node = warp;

    float ds = g_dinv[node];
    float sw = ds * ds;
    uint2 raw = __ldg(&h2[(size_t)node * 32 + lane]);
    float2 f0 = __half22float2(*reinterpret_cast<__half2*>(&raw.x));
    float2 f1 = __half22float2(*reinterpret_cast<__half2*>(&raw.y));
    float4 acc = make_float4(sw * f0.x, sw * f0.y, sw * f1.x, sw * f1.y);

    int e   = g_rowptr[node];
    int end = g_rowptr[node + 1];

    for (; e + 32 <= end; e += 32) {
        int2 cw = g_cw[e + lane];
#pragma unroll
        for (int j = 0; j < 32; j++) {
            int   s  = __shfl_sync(0xffffffffu, cw.x, j);
            float ww = __int_as_float(__shfl_sync(0xffffffffu, cw.y, j));
            uint2 r  = __ldg(&h2[(size_t)s * 32 + lane]);
            float2 a0 = __half22float2(*reinterpret_cast<__half2*>(&r.x));
            float2 a1 = __half22float2(*reinterpret_cast<__half2*>(&r.y));
            acc.x += ww * a0.x; acc.y += ww * a0.y;
            acc.z += ww * a1.x; acc.w += ww * a1.y;
        }
    }
    if (e < end) {
        int rem = end - e;
        int2 cw = (lane < rem) ? g_cw[e + lane] : make_int2(0, 0);
#pragma unroll 4
        for (int j = 0; j < rem; j++) {
            int   s  = __shfl_sync(0xffffffffu, cw.x, j);
            float ww = __int_as_float(__shfl_sync(0xffffffffu, cw.y, j));
            uint2 r  = __ldg(&h2[(size_t)s * 32 + lane]);
            float2 a0 = __half22float2(*reinterpret_cast<__half2*>(&r.x));
            float2 a1 = __half22float2(*reinterpret_cast<__half2*>(&r.y));
            acc.x += ww * a0.x; acc.y += ww * a0.y;
            acc.z += ww * a1.x; acc.w += ww * a1.y;
        }
    }

    float4 b = reinterpret_cast<const float4*>(bias)[lane];
    float4 o;
    o.x = fmaxf(acc.x + b.x, 0.f);
    o.y = fmaxf(acc.y + b.y, 0.f);
    o.z = fmaxf(acc.z + b.z, 0.f);
    o.w = fmaxf(acc.w + b.w, 0.f);
    out4[(size_t)node * 32 + lane] = o;
}

// ---------------- aggregation layer 2 fused with classifier --------------
// o = relu(b2 + agg);  out[node, :16] = o @ Wc + bc
// Wc held in registers: lane owns h-cols c0..c0+3 -> wr[j] = Wc[c0..c0+3][j].
__global__ void __launch_bounds__(256) aggregate2_cls_kernel(
    const uint2* __restrict__ h2, const float* __restrict__ bias,
    const float* __restrict__ Wc, const float* __restrict__ bc,
    float* __restrict__ out, int n)
{
    int warp = (blockIdx.x * blockDim.x + threadIdx.x) >> 5;
    int lane = threadIdx.x & 31;
    if (warp >= n) return;
    int node = warp;
    int c0 = lane * 4;

    float4 wr[16];
#pragma unroll
    for (int j = 0; j < 16; j++)
        wr[j] = make_float4(__ldg(&Wc[(c0 + 0) * 16 + j]),
                            __ldg(&Wc[(c0 + 1) * 16 + j]),
                            __ldg(&Wc[(c0 + 2) * 16 + j]),
                            __ldg(&Wc[(c0 + 3) * 16 + j]));

    float ds = g_dinv[node];
    float sw = ds * ds;
    uint2 raw = __ldg(&h2[(size_t)node * 32 + lane]);
    float2 f0 = __half22float2(*reinterpret_cast<__half2*>(&raw.x));
    float2 f1 = __half22float2(*reinterpret_cast<__half2*>(&raw.y));
    float4 acc = make_float4(sw * f0.x, sw * f0.y, sw * f1.x, sw * f1.y);

    int e   = g_rowptr[node];
    int end = g_rowptr[node + 1];

    for (; e + 32 <= end; e += 32) {
        int2 cw = g_cw[e + lane];
#pragma unroll
        for (int j = 0; j < 32; j++) {
            int   s  = __shfl_sync(0xffffffffu, cw.x, j);
            float ww = __int_as_float(__shfl_sync(0xffffffffu, cw.y, j));
            uint2 r  = __ldg(&h2[(size_t)s * 32 + lane]);
            float2 a0 = __half22float2(*reinterpret_cast<__half2*>(&r.x));
            float2 a1 = __half22float2(*reinterpret_cast<__half2*>(&r.y));
            acc.x += ww * a0.x; acc.y += ww * a0.y;
            acc.z += ww * a1.x; acc.w += ww * a1.y;
        }
    }
    if (e < end) {
        int rem = end - e;
        int2 cw = (lane < rem) ? g_cw[e + lane] : make_int2(0, 0);
#pragma unroll 4
        for (int j = 0; j < rem; j++) {
            int   s  = __shfl_sync(0xffffffffu, cw.x, j);
            float ww = __int_as_float(__shfl_sync(0xffffffffu, cw.y, j));
            uint2 r  = __ldg(&h2[(size_t)s * 32 + lane]);
            float2 a0 = __half22float2(*reinterpret_cast<__half2*>(&r.x));
            float2 a1 = __half22float2(*reinterpret_cast<__half2*>(&r.y));
            acc.x += ww * a0.x; acc.y += ww * a0.y;
            acc.z += ww * a1.x; acc.w += ww * a1.y;
        }
    }

    float4 b = reinterpret_cast<const float4*>(bias)[lane];
    float4 o;
    o.x = fmaxf(acc.x + b.x, 0.f);
    o.y = fmaxf(acc.y + b.y, 0.f);
    o.z = fmaxf(acc.z + b.z, 0.f);
    o.w = fmaxf(acc.w + b.w, 0.f);

    float p[16];
#pragma unroll
    for (int j = 0; j < 16; j++)
        p[j] = o.x * wr[j].x + o.y * wr[j].y + o.z * wr[j].z + o.w * wr[j].w;

#pragma unroll
    for (int off = 16; off > 0; off >>= 1)
#pragma unroll
        for (int j = 0; j < 16; j++)
            p[j] += __shfl_xor_sync(0xffffffffu, p[j], off);

    if (lane == 0) {
        float4 bc0 = reinterpret_cast<const float4*>(bc)[0];
        float4 bc1 = reinterpret_cast<const float4*>(bc)[1];
        float4 bc2 = reinterpret_cast<const float4*>(bc)[2];
        float4 bc3 = reinterpret_cast<const float4*>(bc)[3];
        float4* o4 = reinterpret_cast<float4*>(&out[(size_t)node * 16]);
        o4[0] = make_float4(p[0] + bc0.x,  p[1] + bc0.y,  p[2] + bc0.z,  p[3] + bc0.w);
        o4[1] = make_float4(p[4] + bc1.x,  p[5] + bc1.y,  p[6] + bc1.z,  p[7] + bc1.w);
        o4[2] = make_float4(p[8] + bc2.x,  p[9] + bc2.y,  p[10] + bc2.z, p[11] + bc2.w);
        o4[3] = make_float4(p[12] + bc3.x, p[13] + bc3.y, p[14] + bc3.z, p[15] + bc3.w);
    }
}

// ---------------- launch ----------------
extern "C" void kernel_launch(void* const* d_in, const int* in_sizes, int n_in,
                              void* d_out, int out_size)
{
    const float* x  = (const float*)d_in[0];
    const void*  ei = d_in[1];
    const float* W1 = (const float*)d_in[2];
    const float* b1 = (const float*)d_in[3];
    const float* W2 = (const float*)d_in[4];
    const float* b2 = (const float*)d_in[5];
    const float* Wc = (const float*)d_in[6];
    const float* bc = (const float*)d_in[7];
    float* out = (float*)d_out;

    int n = in_sizes[0] / 128;
    int e = in_sizes[1] / 2;

    __half* h;
    float*  a;
    cudaGetSymbolAddress((void**)&h, g_h);
    cudaGetSymbolAddress((void**)&a, g_a);

    int nb1024 = (n + 1023) / 1024;
    int ebk2   = ((e + 1) / 2 + 255) / 256;

    detect_width_kernel<<<1, 256>>>((const unsigned int*)ei);
    zero_deg_kernel<<<nb1024, 1024>>>(n);
    count_deg_kernel<<<ebk2, 256>>>(ei, e);
    dinv_kernel<<<nb1024, 1024>>>(n);
    scan_part_kernel<<<nb1024, 1024>>>(n);
    scan_top_kernel<<<1, 32>>>(nb1024);
    scan_final_kernel<<<nb1024, 1024>>>(n);
    build_csr_kernel<<<ebk2, 256>>>(ei, e);

    // layer 1
    gemm128_kernel<<<(n + 63) / 64, 256>>>(x, W1, h, n);
    aggregate1_kernel<<<(n + 7) / 8, 256>>>((const uint2*)h, b1, (float4*)a, n);
    // layer 2 + classifier (fused)
    gemm128_kernel<<<(n + 63) / 64, 256>>>(a, W2, h, n);
    aggregate2_cls_kernel<<<(n + 7) / 8, 256>>>((const uint2*)h, b2, Wc, bc, out, n);
}

// round 4
// speedup vs baseline: 2.0946x; 2.0946x over previous
#include <cuda_runtime.h>

// ---------------- problem-size constants ----------------
#define NMAX 50000
#define EMAX 1600000

// ---------------- scratch (device globals: no allocation allowed) --------
__device__ int   g_deg[NMAX];
__device__ float g_dinv[NMAX];
__device__ int   g_rowptr[NMAX + 1];
__device__ int   g_cursor[NMAX];
__device__ int2  g_cw[EMAX];                     // packed (src, w-bits)
__device__ __align__(16) float g_h[(size_t)NMAX * 128];
__device__ __align__(16) float g_a[(size_t)NMAX * 128];
__device__ int g_bsum[64];
__device__ int g_boff[64];
__device__ int g_is64;   // 1 if edge_index is int64, 0 if int32

// ---------------- packed fp32x2 helpers (Blackwell FFMA2) ----------------
__device__ __forceinline__ unsigned long long pack2(float lo, float hi) {
    unsigned long long r;
    asm("mov.b64 %0, {%1, %2};"
        : "=l"(r) : "r"(__float_as_uint(lo)), "r"(__float_as_uint(hi)));
    return r;
}
__device__ __forceinline__ void unpack2(unsigned long long v, float &lo, float &hi) {
    unsigned int a, b;
    asm("mov.b64 {%0, %1}, %2;" : "=r"(a), "=r"(b) : "l"(v));
    lo = __uint_as_float(a);
    hi = __uint_as_float(b);
}
__device__ __forceinline__ void ffma2(unsigned long long &d,
                                      unsigned long long a,
                                      unsigned long long b) {
    asm("fma.rn.f32x2 %0, %1, %2, %0;" : "+l"(d) : "l"(a), "l"(b));
}

// ---------------- edge-index width detection ----------------
__global__ void detect_width_kernel(const unsigned int* __restrict__ p) {
    __shared__ int any;
    if (threadIdx.x == 0) any = 0;
    __syncthreads();
    for (int i = threadIdx.x; i < 2048; i += blockDim.x) {
        if (p[2 * i + 1] != 0u) any = 1;
    }
    __syncthreads();
    if (threadIdx.x == 0) g_is64 = any ? 0 : 1;
}

// ---------------- degree / normalization ----------------
__global__ void zero_deg_kernel(int n) {
    int i = blockIdx.x * blockDim.x + threadIdx.x;
    if (i < n) g_deg[i] = 0;
}

// dst-only degree count, 2 edges per thread (vectorized)
__global__ void count_deg_kernel(const void* __restrict__ ei, int e_total) {
    int t = blockIdx.x * blockDim.x + threadIdx.x;
    int base = t * 2;
    if (base >= e_total) return;
    int d0, d1;
    bool two = (base + 1 < e_total);
    if (g_is64) {
        const long long* p = (const long long*)ei + e_total;   // dst half
        if (two) {
            longlong2 v = *reinterpret_cast<const longlong2*>(p + base);
            d0 = (int)v.x; d1 = (int)v.y;
        } else { d0 = (int)p[base]; d1 = -1; }
    } else {
        const int* p = (const int*)ei + e_total;
        if (two) {
            int2 v = *reinterpret_cast<const int2*>(p + base);
            d0 = v.x; d1 = v.y;
        } else { d0 = p[base]; d1 = -1; }
    }
    atomicAdd(&g_deg[d0], 1);
    if (two) atomicAdd(&g_deg[d1], 1);
}

__global__ void dinv_kernel(int n) {
    int i = blockIdx.x * blockDim.x + threadIdx.x;
    if (i < n) g_dinv[i] = rsqrtf((float)(g_deg[i] + 1));  // +1 self loop
}

// ---------------- 3-kernel exclusive scan of g_deg -> g_rowptr -----------
__global__ void scan_part_kernel(int n) {
    __shared__ int sm[1024];
    int i = blockIdx.x * 1024 + threadIdx.x;
    sm[threadIdx.x] = (i < n) ? g_deg[i] : 0;
    __syncthreads();
    for (int s = 512; s > 0; s >>= 1) {
        if (threadIdx.x < s) sm[threadIdx.x] += sm[threadIdx.x + s];
        __syncthreads();
    }
    if (threadIdx.x == 0) g_bsum[blockIdx.x] = sm[0];
}

__global__ void scan_top_kernel(int nblocks) {
    if (threadIdx.x == 0 && blockIdx.x == 0) {
        int run = 0;
        for (int b = 0; b < nblocks; b++) {
            g_boff[b] = run;
            run += g_bsum[b];
        }
    }
}

__global__ void scan_final_kernel(int n) {
    __shared__ int sm[1024];
    int tid = threadIdx.x;
    int i = blockIdx.x * 1024 + tid;
    int v = (i < n) ? g_deg[i] : 0;
    sm[tid] = v;
    __syncthreads();
    for (int off = 1; off < 1024; off <<= 1) {
        int t = (tid >= off) ? sm[tid - off] : 0;
        __syncthreads();
        sm[tid] += t;
        __syncthreads();
    }
    if (i < n) {
        int start = g_boff[blockIdx.x] + sm[tid] - v;   // exclusive
        g_rowptr[i] = start;
        g_cursor[i] = start;
        if (i == n - 1) g_rowptr[n] = start + v;
    }
}

// ---------------- CSC build (dst-sorted edges), 2 edges per thread -------
__global__ void build_csr_kernel(const void* __restrict__ ei, int e_total) {
    int t = blockIdx.x * blockDim.x + threadIdx.x;
    int base = t * 2;
    if (base >= e_total) return;
    int s0, d0, s1 = 0, d1 = 0;
    bool two = (base + 1 < e_total);
    if (g_is64) {
        const long long* ps = (const long long*)ei;
        const long long* pd = ps + e_total;
        if (two) {
            longlong2 sv = *reinterpret_cast<const longlong2*>(ps + base);
            longlong2 dv = *reinterpret_cast<const longlong2*>(pd + base);
            s0 = (int)sv.x; s1 = (int)sv.y;
            d0 = (int)dv.x; d1 = (int)dv.y;
        } else { s0 = (int)ps[base]; d0 = (int)pd[base]; }
    } else {
        const int* ps = (const int*)ei;
        const int* pd = ps + e_total;
        if (two) {
            int2 sv = *reinterpret_cast<const int2*>(ps + base);
            int2 dv = *reinterpret_cast<const int2*>(pd + base);
            s0 = sv.x; s1 = sv.y;
            d0 = dv.x; d1 = dv.y;
        } else { s0 = ps[base]; d0 = pd[base]; }
    }
    {
        int pos = atomicAdd(&g_cursor[d0], 1);
        float w = g_dinv[s0] * g_dinv[d0];
        g_cw[pos] = make_int2(s0, __float_as_int(w));
    }
    if (two) {
        int pos = atomicAdd(&g_cursor[d1], 1);
        float w = g_dinv[s1] * g_dinv[d1];
        g_cw[pos] = make_int2(s1, __float_as_int(w));
    }
}

// ---------------- GEMM: C[M,128] = A[M,128] @ W[128,128], packed f32x2 ----
// Block: 64 rows x 128 cols, 256 threads, each thread 4 rows x 4 col-pairs.
__global__ void __launch_bounds__(256) gemm128_kernel(
    const float* __restrict__ A, const float* __restrict__ W,
    float* __restrict__ C, int M)
{
    __shared__ unsigned long long xs[64][33];   // packed (v, v), padded
    __shared__ unsigned long long ws[32][64];   // packed (W[k][2cp], W[k][2cp+1])

    int tid  = threadIdx.x;
    int row0 = blockIdx.x * 64;
    int cpg  = tid & 15;        // col-pair group: cp = 16*j + cpg
    int rg   = tid >> 4;        // row group: rows rg*4 + i

    unsigned long long acc[4][4];
#pragma unroll
    for (int i = 0; i < 4; i++)
#pragma unroll
        for (int j = 0; j < 4; j++) acc[i][j] = 0ull;

    for (int kb = 0; kb < 128; kb += 32) {
        {
            int lr = tid >> 5;
            int lk = tid & 31;
#pragma unroll
            for (int p = 0; p < 8; p++) {
                int r = lr + p * 8;
                int grow = row0 + r;
                float v = (grow < M) ? A[(size_t)grow * 128 + kb + lk] : 0.f;
                xs[r][lk] = pack2(v, v);
            }
        }
        {
#pragma unroll
            for (int p = 0; p < 8; p++) {
                int idx = p * 256 + tid;
                int kk = idx >> 6;
                int cp = idx & 63;
                float2 wv = *reinterpret_cast<const float2*>(&W[(kb + kk) * 128 + cp * 2]);
                ws[kk][cp] = pack2(wv.x, wv.y);
            }
        }
        __syncthreads();

#pragma unroll
        for (int kk = 0; kk < 32; kk++) {
            unsigned long long wv[4], xv[4];
#pragma unroll
            for (int j = 0; j < 4; j++) wv[j] = ws[kk][16 * j + cpg];
#pragma unroll
            for (int i = 0; i < 4; i++) xv[i] = xs[rg * 4 + i][kk];
#pragma unroll
            for (int i = 0; i < 4; i++)
#pragma unroll
                for (int j = 0; j < 4; j++) ffma2(acc[i][j], xv[i], wv[j]);
        }
        __syncthreads();
    }

#pragma unroll
    for (int i = 0; i < 4; i++) {
        int grow = row0 + rg * 4 + i;
        if (grow < M) {
#pragma unroll
            for (int j = 0; j < 4; j++) {
                int cp = 16 * j + cpg;
                float lo, hi;
                unpack2(acc[i][j], lo, hi);
                *reinterpret_cast<float2*>(&C[(size_t)grow * 128 + cp * 2]) =
                    make_float2(lo, hi);
            }
        }
    }
}

// ---------------- aggregation: out = relu(bias + dinv^2*h[i] + sum w*h[src])
// One warp per node; lane handles 4 cols via float4. Edge data: one LDG.64.
__global__ void __launch_bounds__(256) aggregate_kernel(
    const float4* __restrict__ h4, const float* __restrict__ bias,
    float4* __restrict__ out4, int n)
{
    int warp = (blockIdx.x * blockDim.x + threadIdx.x) >> 5;
    int lane = threadIdx.x & 31;
    if (warp >= n) return;
    int node = warp;

    float ds = g_dinv[node];
    float sw = ds * ds;                       // 1/deg (self-loop norm)
    float4 hv = h4[(size_t)node * 32 + lane];
    float4 acc;
    acc.x = sw * hv.x; acc.y = sw * hv.y; acc.z = sw * hv.z; acc.w = sw * hv.w;

    int e   = g_rowptr[node];
    int end = g_rowptr[node + 1];

    for (; e + 32 <= end; e += 32) {
        int2 cw = g_cw[e + lane];
#pragma unroll
        for (int j = 0; j < 32; j++) {
            int   s  = __shfl_sync(0xffffffffu, cw.x, j);
            float ww = __int_as_float(__shfl_sync(0xffffffffu, cw.y, j));
            float4 hj = h4[(size_t)s * 32 + lane];
            acc.x += ww * hj.x; acc.y += ww * hj.y;
            acc.z += ww * hj.z; acc.w += ww * hj.w;
        }
    }
    if (e < end) {
        int rem = end - e;
        int2 cw = (lane < rem) ? g_cw[e + lane] : make_int2(0, 0);
#pragma unroll 4
        for (int j = 0; j < rem; j++) {
            int   s  = __shfl_sync(0xffffffffu, cw.x, j);
            float ww = __int_as_float(__shfl_sync(0xffffffffu, cw.y, j));
            float4 hj = h4[(size_t)s * 32 + lane];
            acc.x += ww * hj.x; acc.y += ww * hj.y;
            acc.z += ww * hj.z; acc.w += ww * hj.w;
        }
    }

    float4 b = reinterpret_cast<const float4*>(bias)[lane];
    float4 o;
    o.x = fmaxf(acc.x + b.x, 0.f);
    o.y = fmaxf(acc.y + b.y, 0.f);
    o.z = fmaxf(acc.z + b.z, 0.f);
    o.w = fmaxf(acc.w + b.w, 0.f);
    out4[(size_t)node * 32 + lane] = o;
}

// ---------------- classifier: out[M,16] = h[M,128] @ Wc[128,16] + bc ------
__global__ void __launch_bounds__(256) classifier_kernel(
    const float* __restrict__ h, const float* __restrict__ Wc,
    const float* __restrict__ bc, float* __restrict__ out, int n)
{
    __shared__ float ws[128 * 16];
    __shared__ float hs[16][129];
    int tid = threadIdx.x;
    int row0 = blockIdx.x * 16;
#pragma unroll
    for (int p = 0; p < 8; p++) ws[p * 256 + tid] = Wc[p * 256 + tid];
#pragma unroll
    for (int p = 0; p < 8; p++) {
        int idx = p * 256 + tid;
        int r = idx >> 7, c = idx & 127;
        hs[r][c] = (row0 + r < n) ? h[(size_t)(row0 + r) * 128 + c] : 0.f;
    }
    __syncthreads();
    int r = tid >> 4, c = tid & 15;
    float acc = bc[c];
#pragma unroll 16
    for (int k = 0; k < 128; k++) acc = fmaf(hs[r][k], ws[k * 16 + c], acc);
    if (row0 + r < n) out[(size_t)(row0 + r) * 16 + c] = acc;
}

// ---------------- launch ----------------
extern "C" void kernel_launch(void* const* d_in, const int* in_sizes, int n_in,
                              void* d_out, int out_size)
{
    const float* x  = (const float*)d_in[0];
    const void*  ei = d_in[1];
    const float* W1 = (const float*)d_in[2];
    const float* b1 = (const float*)d_in[3];
    const float* W2 = (const float*)d_in[4];
    const float* b2 = (const float*)d_in[5];
    const float* Wc = (const float*)d_in[6];
    const float* bc = (const float*)d_in[7];
    float* out = (float*)d_out;

    int n = in_sizes[0] / 128;
    int e = in_sizes[1] / 2;

    float *h, *a;
    cudaGetSymbolAddress((void**)&h, g_h);
    cudaGetSymbolAddress((void**)&a, g_a);

    int nb1024 = (n + 1023) / 1024;
    int ebk2   = ((e + 1) / 2 + 255) / 256;

    detect_width_kernel<<<1, 256>>>((const unsigned int*)ei);
    zero_deg_kernel<<<nb1024, 1024>>>(n);
    count_deg_kernel<<<ebk2, 256>>>(ei, e);
    dinv_kernel<<<nb1024, 1024>>>(n);
    scan_part_kernel<<<nb1024, 1024>>>(n);
    scan_top_kernel<<<1, 32>>>(nb1024);
    scan_final_kernel<<<nb1024, 1024>>>(n);
    build_csr_kernel<<<ebk2, 256>>>(ei, e);

    // layer 1
    gemm128_kernel<<<(n + 63) / 64, 256>>>(x, W1, h, n);
    aggregate_kernel<<<(n + 7) / 8, 256>>>((const float4*)h, b1, (float4*)a, n);
    // layer 2
    gemm128_kernel<<<(n + 63) / 64, 256>>>(a, W2, h, n);
    aggregate_kernel<<<(n + 7) / 8, 256>>>((const float4*)h, b2, (float4*)a, n);
    // classifier
    classifier_kernel<<<(n + 15) / 16, 256>>>(a, Wc, bc, out, n);
}

// round 5
// speedup vs baseline: 2.2787x; 1.0879x over previous
#include <cuda_runtime.h>
#include <cuda_fp16.h>

// ---------------- problem-size constants ----------------
#define NMAX 50000
#define EMAX 1600000

// ---------------- scratch (device globals: no allocation allowed) --------
__device__ int   g_deg[NMAX];
__device__ float g_dinv[NMAX];
__device__ int   g_rowptr[NMAX + 1];
__device__ int   g_cursor[NMAX];
__device__ int2  g_cw[EMAX];                     // packed (src, w-bits)
__device__ __align__(16) __half g_h[(size_t)NMAX * 128];   // fp16 gather operand
__device__ __align__(16) float  g_a[(size_t)NMAX * 128];   // fp32 inter-layer
__device__ int g_bsum[64];
__device__ int g_boff[64];
__device__ int g_is64;   // 1 if edge_index is int64, 0 if int32

// ---------------- packed fp32x2 helpers (Blackwell FFMA2) ----------------
__device__ __forceinline__ unsigned long long pack2(float lo, float hi) {
    unsigned long long r;
    asm("mov.b64 %0, {%1, %2};"
        : "=l"(r) : "r"(__float_as_uint(lo)), "r"(__float_as_uint(hi)));
    return r;
}
__device__ __forceinline__ void unpack2(unsigned long long v, float &lo, float &hi) {
    unsigned int a, b;
    asm("mov.b64 {%0, %1}, %2;" : "=r"(a), "=r"(b) : "l"(v));
    lo = __uint_as_float(a);
    hi = __uint_as_float(b);
}
__device__ __forceinline__ void ffma2(unsigned long long &d,
                                      unsigned long long a,
                                      unsigned long long b) {
    asm("fma.rn.f32x2 %0, %1, %2, %0;" : "+l"(d) : "l"(a), "l"(b));
}

// ---------------- edge-index width detection ----------------
__global__ void detect_width_kernel(const unsigned int* __restrict__ p) {
    __shared__ int any;
    if (threadIdx.x == 0) any = 0;
    __syncthreads();
    for (int i = threadIdx.x; i < 2048; i += blockDim.x) {
        if (p[2 * i + 1] != 0u) any = 1;
    }
    __syncthreads();
    if (threadIdx.x == 0) g_is64 = any ? 0 : 1;
}

// ---------------- degree / normalization ----------------
__global__ void zero_deg_kernel(int n) {
    int i = blockIdx.x * blockDim.x + threadIdx.x;
    if (i < n) g_deg[i] = 0;
}

// dst-only degree count, 2 edges per thread (vectorized)
__global__ void count_deg_kernel(const void* __restrict__ ei, int e_total) {
    int t = blockIdx.x * blockDim.x + threadIdx.x;
    int base = t * 2;
    if (base >= e_total) return;
    int d0, d1;
    bool two = (base + 1 < e_total);
    if (g_is64) {
        const long long* p = (const long long*)ei + e_total;   // dst half
        if (two) {
            longlong2 v = *reinterpret_cast<const longlong2*>(p + base);
            d0 = (int)v.x; d1 = (int)v.y;
        } else { d0 = (int)p[base]; d1 = -1; }
    } else {
        const int* p = (const int*)ei + e_total;
        if (two) {
            int2 v = *reinterpret_cast<const int2*>(p + base);
            d0 = v.x; d1 = v.y;
        } else { d0 = p[base]; d1 = -1; }
    }
    atomicAdd(&g_deg[d0], 1);
    if (two) atomicAdd(&g_deg[d1], 1);
}

__global__ void dinv_kernel(int n) {
    int i = blockIdx.x * blockDim.x + threadIdx.x;
    if (i < n) g_dinv[i] = rsqrtf((float)(g_deg[i] + 1));  // +1 self loop
}

// ---------------- 3-kernel exclusive scan of g_deg -> g_rowptr -----------
__global__ void scan_part_kernel(int n) {
    __shared__ int sm[1024];
    int i = blockIdx.x * 1024 + threadIdx.x;
    sm[threadIdx.x] = (i < n) ? g_deg[i] : 0;
    __syncthreads();
    for (int s = 512; s > 0; s >>= 1) {
        if (threadIdx.x < s) sm[threadIdx.x] += sm[threadIdx.x + s];
        __syncthreads();
    }
    if (threadIdx.x == 0) g_bsum[blockIdx.x] = sm[0];
}

__global__ void scan_top_kernel(int nblocks) {
    if (threadIdx.x == 0 && blockIdx.x == 0) {
        int run = 0;
        for (int b = 0; b < nblocks; b++) {
            g_boff[b] = run;
            run += g_bsum[b];
        }
    }
}

__global__ void scan_final_kernel(int n) {
    __shared__ int sm[1024];
    int tid = threadIdx.x;
    int i = blockIdx.x * 1024 + tid;
    int v = (i < n) ? g_deg[i] : 0;
    sm[tid] = v;
    __syncthreads();
    for (int off = 1; off < 1024; off <<= 1) {
        int t = (tid >= off) ? sm[tid - off] : 0;
        __syncthreads();
        sm[tid] += t;
        __syncthreads();
    }
    if (i < n) {
        int start = g_boff[blockIdx.x] + sm[tid] - v;   // exclusive
        g_rowptr[i] = start;
        g_cursor[i] = start;
        if (i == n - 1) g_rowptr[n] = start + v;
    }
}

// ---------------- CSC build (dst-sorted edges), 2 edges per thread -------
__global__ void build_csr_kernel(const void* __restrict__ ei, int e_total) {
    int t = blockIdx.x * blockDim.x + threadIdx.x;
    int base = t * 2;
    if (base >= e_total) return;
    int s0, d0, s1 = 0, d1 = 0;
    bool two = (base + 1 < e_total);
    if (g_is64) {
        const long long* ps = (const long long*)ei;
        const long long* pd = ps + e_total;
        if (two) {
            longlong2 sv = *reinterpret_cast<const longlong2*>(ps + base);
            longlong2 dv = *reinterpret_cast<const longlong2*>(pd + base);
            s0 = (int)sv.x; s1 = (int)sv.y;
            d0 = (int)dv.x; d1 = (int)dv.y;
        } else { s0 = (int)ps[base]; d0 = (int)pd[base]; }
    } else {
        const int* ps = (const int*)ei;
        const int* pd = ps + e_total;
        if (two) {
            int2 sv = *reinterpret_cast<const int2*>(ps + base);
            int2 dv = *reinterpret_cast<const int2*>(pd + base);
            s0 = sv.x; s1 = sv.y;
            d0 = dv.x; d1 = dv.y;
        } else { s0 = ps[base]; d0 = pd[base]; }
    }
    {
        int pos = atomicAdd(&g_cursor[d0], 1);
        float w = g_dinv[s0] * g_dinv[d0];
        g_cw[pos] = make_int2(s0, __float_as_int(w));
    }
    if (two) {
        int pos = atomicAdd(&g_cursor[d1], 1);
        float w = g_dinv[s1] * g_dinv[d1];
        g_cw[pos] = make_int2(s1, __float_as_int(w));
    }
}

// ---------------- GEMM: C[M,128] = A[M,128] @ W[128,128] -> fp16 store ---
// Block: 64 rows x 128 cols, 256 threads, each thread 4 rows x 4 col-pairs.
__global__ void __launch_bounds__(256) gemm128_kernel(
    const float* __restrict__ A, const float* __restrict__ W,
    __half* __restrict__ C, int M)
{
    __shared__ unsigned long long xs[64][33];   // packed (v, v), padded
    __shared__ unsigned long long ws[32][64];   // packed (W[k][2cp], W[k][2cp+1])

    int tid  = threadIdx.x;
    int row0 = blockIdx.x * 64;
    int cpg  = tid & 15;        // col-pair group: cp = 16*j + cpg
    int rg   = tid >> 4;        // row group: rows rg*4 + i

    unsigned long long acc[4][4];
#pragma unroll
    for (int i = 0; i < 4; i++)
#pragma unroll
        for (int j = 0; j < 4; j++) acc[i][j] = 0ull;

    for (int kb = 0; kb < 128; kb += 32) {
        {
            int lr = tid >> 5;
            int lk = tid & 31;
#pragma unroll
            for (int p = 0; p < 8; p++) {
                int r = lr + p * 8;
                int grow = row0 + r;
                float v = (grow < M) ? A[(size_t)grow * 128 + kb + lk] : 0.f;
                xs[r][lk] = pack2(v, v);
            }
        }
        {
#pragma unroll
            for (int p = 0; p < 8; p++) {
                int idx = p * 256 + tid;
                int kk = idx >> 6;
                int cp = idx & 63;
                float2 wv = *reinterpret_cast<const float2*>(&W[(kb + kk) * 128 + cp * 2]);
                ws[kk][cp] = pack2(wv.x, wv.y);
            }
        }
        __syncthreads();

#pragma unroll
        for (int kk = 0; kk < 32; kk++) {
            unsigned long long wv[4], xv[4];
#pragma unroll
            for (int j = 0; j < 4; j++) wv[j] = ws[kk][16 * j + cpg];
#pragma unroll
            for (int i = 0; i < 4; i++) xv[i] = xs[rg * 4 + i][kk];
#pragma unroll
            for (int i = 0; i < 4; i++)
#pragma unroll
                for (int j = 0; j < 4; j++) ffma2(acc[i][j], xv[i], wv[j]);
        }
        __syncthreads();
    }

#pragma unroll
    for (int i = 0; i < 4; i++) {
        int grow = row0 + rg * 4 + i;
        if (grow < M) {
#pragma unroll
            for (int j = 0; j < 4; j++) {
                int cp = 16 * j + cpg;
                float lo, hi;
                unpack2(acc[i][j], lo, hi);
                *reinterpret_cast<__half2*>(&C[(size_t)grow * 128 + cp * 2]) =
                    __floats2half2_rn(lo, hi);
            }
        }
    }
}

// ---------------- aggregation: out = relu(bias + dinv^2*h[i] + sum w*h[src])
// One warp per node; lane handles 4 cols (8B fp16). fp32 accumulation.
__global__ void __launch_bounds__(256) aggregate_kernel(
    const uint2* __restrict__ h2, const float* __restrict__ bias,
    float4* __restrict__ out4, int n)
{
    int warp = (blockIdx.x * blockDim.x + threadIdx.x) >> 5;
    int lane = threadIdx.x & 31;
    if (warp >= n) return;
    int node = warp;

    float ds = g_dinv[node];
    float sw = ds * ds;                       // 1/deg (self-loop norm)
    uint2 raw = h2[(size_t)node * 32 + lane];
    float2 f0 = __half22float2(*reinterpret_cast<__half2*>(&raw.x));
    float2 f1 = __half22float2(*reinterpret_cast<__half2*>(&raw.y));
    float4 acc = make_float4(sw * f0.x, sw * f0.y, sw * f1.x, sw * f1.y);

    int e   = g_rowptr[node];
    int end = g_rowptr[node + 1];

    for (; e + 32 <= end; e += 32) {
        int2 cw = g_cw[e + lane];
#pragma unroll
        for (int j = 0; j < 32; j++) {
            int   s  = __shfl_sync(0xffffffffu, cw.x, j);
            float ww = __int_as_float(__shfl_sync(0xffffffffu, cw.y, j));
            uint2 r  = h2[(size_t)s * 32 + lane];
            float2 a0 = __half22float2(*reinterpret_cast<__half2*>(&r.x));
            float2 a1 = __half22float2(*reinterpret_cast<__half2*>(&r.y));
            acc.x += ww * a0.x; acc.y += ww * a0.y;
            acc.z += ww * a1.x; acc.w += ww * a1.y;
        }
    }
    if (e < end) {
        int rem = end - e;
        int2 cw = (lane < rem) ? g_cw[e + lane] : make_int2(0, 0);
#pragma unroll 4
        for (int j = 0; j < rem; j++) {
            int   s  = __shfl_sync(0xffffffffu, cw.x, j);
            float ww = __int_as_float(__shfl_sync(0xffffffffu, cw.y, j));
            uint2 r  = h2[(size_t)s * 32 + lane];
            float2 a0 = __half22float2(*reinterpret_cast<__half2*>(&r.x));
            float2 a1 = __half22float2(*reinterpret_cast<__half2*>(&r.y));
            acc.x += ww * a0.x; acc.y += ww * a0.y;
            acc.z += ww * a1.x; acc.w += ww * a1.y;
        }
    }

    float4 b = reinterpret_cast<const float4*>(bias)[lane];
    float4 o;
    o.x = fmaxf(acc.x + b.x, 0.f);
    o.y = fmaxf(acc.y + b.y, 0.f);
    o.z = fmaxf(acc.z + b.z, 0.f);
    o.w = fmaxf(acc.w + b.w, 0.f);
    out4[(size_t)node * 32 + lane] = o;
}

// ---------------- classifier: out[M,16] = h[M,128] @ Wc[128,16] + bc ------
__global__ void __launch_bounds__(256) classifier_kernel(
    const float* __restrict__ h, const float* __restrict__ Wc,
    const float* __restrict__ bc, float* __restrict__ out, int n)
{
    __shared__ float ws[128 * 16];
    __shared__ float hs[16][129];
    int tid = threadIdx.x;
    int row0 = blockIdx.x * 16;
#pragma unroll
    for (int p = 0; p < 8; p++) ws[p * 256 + tid] = Wc[p * 256 + tid];
#pragma unroll
    for (int p = 0; p < 8; p++) {
        int idx = p * 256 + tid;
        int r = idx >> 7, c = idx & 127;
        hs[r][c] = (row0 + r < n) ? h[(size_t)(row0 + r) * 128 + c] : 0.f;
    }
    __syncthreads();
    int r = tid >> 4, c = tid & 15;
    float acc = bc[c];
#pragma unroll 16
    for (int k = 0; k < 128; k++) acc = fmaf(hs[r][k], ws[k * 16 + c], acc);
    if (row0 + r < n) out[(size_t)(row0 + r) * 16 + c] = acc;
}

// ---------------- launch ----------------
extern "C" void kernel_launch(void* const* d_in, const int* in_sizes, int n_in,
                              void* d_out, int out_size)
{
    const float* x  = (const float*)d_in[0];
    const void*  ei = d_in[1];
    const float* W1 = (const float*)d_in[2];
    const float* b1 = (const float*)d_in[3];
    const float* W2 = (const float*)d_in[4];
    const float* b2 = (const float*)d_in[5];
    const float* Wc = (const float*)d_in[6];
    const float* bc = (const float*)d_in[7];
    float* out = (float*)d_out;

    int n = in_sizes[0] / 128;
    int e = in_sizes[1] / 2;

    __half* h;
    float*  a;
    cudaGetSymbolAddress((void**)&h, g_h);
    cudaGetSymbolAddress((void**)&a, g_a);

    int nb1024 = (n + 1023) / 1024;
    int ebk2   = ((e + 1) / 2 + 255) / 256;

    detect_width_kernel<<<1, 256>>>((const unsigned int*)ei);
    zero_deg_kernel<<<nb1024, 1024>>>(n);
    count_deg_kernel<<<ebk2, 256>>>(ei, e);
    dinv_kernel<<<nb1024, 1024>>>(n);
    scan_part_kernel<<<nb1024, 1024>>>(n);
    scan_top_kernel<<<1, 32>>>(nb1024);
    scan_final_kernel<<<nb1024, 1024>>>(n);
    build_csr_kernel<<<ebk2, 256>>>(ei, e);

    // layer 1
    gemm128_kernel<<<(n + 63) / 64, 256>>>(x, W1, h, n);
    aggregate_kernel<<<(n + 7) / 8, 256>>>((const uint2*)h, b1, (float4*)a, n);
    // layer 2
    gemm128_kernel<<<(n + 63) / 64, 256>>>(a, W2, h, n);
    aggregate_kernel<<<(n + 7) / 8, 256>>>((const uint2*)h, b2, (float4*)a, n);
    // classifier
    classifier_kernel<<<(n + 15) / 16, 256>>>(a, Wc, bc, out, n);
}

// round 6
// speedup vs baseline: 2.4503x; 1.0753x over previous
#include <cuda_runtime.h>
#include <cuda_fp16.h>

// ---------------- problem-size constants ----------------
#define NMAX 50000
#define EMAX 1600000

// ---------------- scratch (device globals: no allocation allowed) --------
__device__ int   g_deg[NMAX];
__device__ float g_dinv[NMAX];
__device__ int   g_rowptr[NMAX + 1];
__device__ int   g_cursor[NMAX];
__device__ int2  g_cw[EMAX];                     // packed (src, w-bits)
__device__ __align__(16) __half g_h[(size_t)NMAX * 128];   // fp16 gather operand
__device__ __align__(16) float  g_a[(size_t)NMAX * 128];   // fp32 inter-layer
__device__ int g_bsum[64];
__device__ int g_boff[64];
__device__ int g_is64;   // 1 if edge_index is int64, 0 if int32

// ---------------- packed fp32x2 helpers (Blackwell FFMA2) ----------------
__device__ __forceinline__ unsigned long long pack2(float lo, float hi) {
    unsigned long long r;
    asm("mov.b64 %0, {%1, %2};"
        : "=l"(r) : "r"(__float_as_uint(lo)), "r"(__float_as_uint(hi)));
    return r;
}
__device__ __forceinline__ void unpack2(unsigned long long v, float &lo, float &hi) {
    unsigned int a, b;
    asm("mov.b64 {%0, %1}, %2;" : "=r"(a), "=r"(b) : "l"(v));
    lo = __uint_as_float(a);
    hi = __uint_as_float(b);
}
__device__ __forceinline__ void ffma2(unsigned long long &d,
                                      unsigned long long a,
                                      unsigned long long b) {
    asm("fma.rn.f32x2 %0, %1, %2, %0;" : "+l"(d) : "l"(a), "l"(b));
}

// ---------------- init: width detect (block 0) + zero degrees ------------
__global__ void init_kernel(const unsigned int* __restrict__ p, int n) {
    int i = blockIdx.x * blockDim.x + threadIdx.x;
    if (i < n) g_deg[i] = 0;
    if (blockIdx.x == 0) {
        __shared__ int any;
        if (threadIdx.x == 0) any = 0;
        __syncthreads();
        for (int k = threadIdx.x; k < 2048; k += blockDim.x) {
            if (p[2 * k + 1] != 0u) any = 1;
        }
        __syncthreads();
        if (threadIdx.x == 0) g_is64 = any ? 0 : 1;
    }
}

// dst-only degree count, 2 edges per thread (vectorized)
__global__ void count_deg_kernel(const void* __restrict__ ei, int e_total) {
    int t = blockIdx.x * blockDim.x + threadIdx.x;
    int base = t * 2;
    if (base >= e_total) return;
    int d0, d1;
    bool two = (base + 1 < e_total);
    if (g_is64) {
        const long long* p = (const long long*)ei + e_total;   // dst half
        if (two) {
            longlong2 v = *reinterpret_cast<const longlong2*>(p + base);
            d0 = (int)v.x; d1 = (int)v.y;
        } else { d0 = (int)p[base]; d1 = -1; }
    } else {
        const int* p = (const int*)ei + e_total;
        if (two) {
            int2 v = *reinterpret_cast<const int2*>(p + base);
            d0 = v.x; d1 = v.y;
        } else { d0 = p[base]; d1 = -1; }
    }
    atomicAdd(&g_deg[d0], 1);
    if (two) atomicAdd(&g_deg[d1], 1);
}

// ---------------- scan stage 1 (block sums) + dinv fused -----------------
__global__ void scan_part_dinv_kernel(int n) {
    __shared__ int sm[1024];
    int i = blockIdx.x * 1024 + threadIdx.x;
    int v = (i < n) ? g_deg[i] : 0;
    if (i < n) g_dinv[i] = rsqrtf((float)(v + 1));   // +1 self loop
    sm[threadIdx.x] = v;
    __syncthreads();
    for (int s = 512; s > 0; s >>= 1) {
        if (threadIdx.x < s) sm[threadIdx.x] += sm[threadIdx.x + s];
        __syncthreads();
    }
    if (threadIdx.x == 0) g_bsum[blockIdx.x] = sm[0];
}

__global__ void scan_top_kernel(int nblocks) {
    if (threadIdx.x == 0 && blockIdx.x == 0) {
        int run = 0;
        for (int b = 0; b < nblocks; b++) {
            g_boff[b] = run;
            run += g_bsum[b];
        }
    }
}

__global__ void scan_final_kernel(int n) {
    __shared__ int sm[1024];
    int tid = threadIdx.x;
    int i = blockIdx.x * 1024 + tid;
    int v = (i < n) ? g_deg[i] : 0;
    sm[tid] = v;
    __syncthreads();
    for (int off = 1; off < 1024; off <<= 1) {
        int t = (tid >= off) ? sm[tid - off] : 0;
        __syncthreads();
        sm[tid] += t;
        __syncthreads();
    }
    if (i < n) {
        int start = g_boff[blockIdx.x] + sm[tid] - v;   // exclusive
        g_rowptr[i] = start;
        g_cursor[i] = start;
        if (i == n - 1) g_rowptr[n] = start + v;
    }
}

// ---------------- build body (CSC scatter), callable from fat kernel -----
__device__ __forceinline__ void build_body(const void* __restrict__ ei,
                                           int e_total, int t) {
    int base = t * 2;
    if (base >= e_total) return;
    int s0, d0, s1 = 0, d1 = 0;
    bool two = (base + 1 < e_total);
    if (g_is64) {
        const long long* ps = (const long long*)ei;
        const long long* pd = ps + e_total;
        if (two) {
            longlong2 sv = *reinterpret_cast<const longlong2*>(ps + base);
            longlong2 dv = *reinterpret_cast<const longlong2*>(pd + base);
            s0 = (int)sv.x; s1 = (int)sv.y;
            d0 = (int)dv.x; d1 = (int)dv.y;
        } else { s0 = (int)ps[base]; d0 = (int)pd[base]; }
    } else {
        const int* ps = (const int*)ei;
        const int* pd = ps + e_total;
        if (two) {
            int2 sv = *reinterpret_cast<const int2*>(ps + base);
            int2 dv = *reinterpret_cast<const int2*>(pd + base);
            s0 = sv.x; s1 = sv.y;
            d0 = dv.x; d1 = dv.y;
        } else { s0 = ps[base]; d0 = pd[base]; }
    }
    {
        int pos = atomicAdd(&g_cursor[d0], 1);
        float w = g_dinv[s0] * g_dinv[d0];
        g_cw[pos] = make_int2(s0, __float_as_int(w));
    }
    if (two) {
        int pos = atomicAdd(&g_cursor[d1], 1);
        float w = g_dinv[s1] * g_dinv[d1];
        g_cw[pos] = make_int2(s1, __float_as_int(w));
    }
}

// ---------------- GEMM block body: C[64,128] tile, packed f32x2 ----------
// 256 threads, each thread 4 rows x 4 col-pairs. fp16 store.
__device__ __forceinline__ void gemm_block_body(
    const float* __restrict__ A, const float* __restrict__ W,
    __half* __restrict__ C, int M, int blk,
    unsigned long long (*xs)[33], unsigned long long (*ws)[64])
{
    int tid  = threadIdx.x;
    int row0 = blk * 64;
    int cpg  = tid & 15;        // col-pair group: cp = 16*j + cpg
    int rg   = tid >> 4;        // row group: rows rg*4 + i

    unsigned long long acc[4][4];
#pragma unroll
    for (int i = 0; i < 4; i++)
#pragma unroll
        for (int j = 0; j < 4; j++) acc[i][j] = 0ull;

    for (int kb = 0; kb < 128; kb += 32) {
        {
            int lr = tid >> 5;
            int lk = tid & 31;
#pragma unroll
            for (int p = 0; p < 8; p++) {
                int r = lr + p * 8;
                int grow = row0 + r;
                float v = (grow < M) ? A[(size_t)grow * 128 + kb + lk] : 0.f;
                xs[r][lk] = pack2(v, v);
            }
        }
        {
#pragma unroll
            for (int p = 0; p < 8; p++) {
                int idx = p * 256 + tid;
                int kk = idx >> 6;
                int cp = idx & 63;
                float2 wv = *reinterpret_cast<const float2*>(&W[(kb + kk) * 128 + cp * 2]);
                ws[kk][cp] = pack2(wv.x, wv.y);
            }
        }
        __syncthreads();

#pragma unroll
        for (int kk = 0; kk < 32; kk++) {
            unsigned long long wv[4], xv[4];
#pragma unroll
            for (int j = 0; j < 4; j++) wv[j] = ws[kk][16 * j + cpg];
#pragma unroll
            for (int i = 0; i < 4; i++) xv[i] = xs[rg * 4 + i][kk];
#pragma unroll
            for (int i = 0; i < 4; i++)
#pragma unroll
                for (int j = 0; j < 4; j++) ffma2(acc[i][j], xv[i], wv[j]);
        }
        __syncthreads();
    }

#pragma unroll
    for (int i = 0; i < 4; i++) {
        int grow = row0 + rg * 4 + i;
        if (grow < M) {
#pragma unroll
            for (int j = 0; j < 4; j++) {
                int cp = 16 * j + cpg;
                float lo, hi;
                unpack2(acc[i][j], lo, hi);
                *reinterpret_cast<__half2*>(&C[(size_t)grow * 128 + cp * 2]) =
                    __floats2half2_rn(lo, hi);
            }
        }
    }
}

// ---------------- standalone GEMM (layer 2) ----------------
__global__ void __launch_bounds__(256) gemm128_kernel(
    const float* __restrict__ A, const float* __restrict__ W,
    __half* __restrict__ C, int M)
{
    __shared__ unsigned long long xs[64][33];
    __shared__ unsigned long long ws[32][64];
    gemm_block_body(A, W, C, M, blockIdx.x, xs, ws);
}

// ---------------- fat kernel: gemm1 blocks + CSC-build blocks ------------
// blocks [0, gemm_blocks): gemm1 tile; blocks [gemm_blocks, ...): build.
__global__ void __launch_bounds__(256) gemm1_build_kernel(
    const float* __restrict__ A, const float* __restrict__ W,
    __half* __restrict__ C, int M,
    const void* __restrict__ ei, int e_total, int gemm_blocks)
{
    __shared__ unsigned long long xs[64][33];
    __shared__ unsigned long long ws[32][64];
    if (blockIdx.x < gemm_blocks) {
        gemm_block_body(A, W, C, M, blockIdx.x, xs, ws);
    } else {
        int t = (blockIdx.x - gemm_blocks) * blockDim.x + threadIdx.x;
        build_body(ei, e_total, t);
    }
}

// ---------------- aggregation: out = relu(bias + dinv^2*h[i] + sum w*h[src])
// One warp per node; lane handles 4 cols (8B fp16). fp32 accumulation.
__global__ void __launch_bounds__(256) aggregate_kernel(
    const uint2* __restrict__ h2, const float* __restrict__ bias,
    float4* __restrict__ out4, int n)
{
    int warp = (blockIdx.x * blockDim.x + threadIdx.x) >> 5;
    int lane = threadIdx.x & 31;
    if (warp >= n) return;
    int node = warp;

    float ds = g_dinv[node];
    float sw = ds * ds;                       // 1/deg (self-loop norm)
    uint2 raw = h2[(size_t)node * 32 + lane];
    float2 f0 = __half22float2(*reinterpret_cast<__half2*>(&raw.x));
    float2 f1 = __half22float2(*reinterpret_cast<__half2*>(&raw.y));
    float4 acc = make_float4(sw * f0.x, sw * f0.y, sw * f1.x, sw * f1.y);

    int e   = g_rowptr[node];
    int end = g_rowptr[node + 1];

    for (; e + 32 <= end; e += 32) {
        int2 cw = g_cw[e + lane];
#pragma unroll
        for (int j = 0; j < 32; j++) {
            int   s  = __shfl_sync(0xffffffffu, cw.x, j);
            float ww = __int_as_float(__shfl_sync(0xffffffffu, cw.y, j));
            uint2 r  = h2[(size_t)s * 32 + lane];
            float2 a0 = __half22float2(*reinterpret_cast<__half2*>(&r.x));
            float2 a1 = __half22float2(*reinterpret_cast<__half2*>(&r.y));
            acc.x += ww * a0.x; acc.y += ww * a0.y;
            acc.z += ww * a1.x; acc.w += ww * a1.y;
        }
    }
    if (e < end) {
        int rem = end - e;
        int2 cw = (lane < rem) ? g_cw[e + lane] : make_int2(0, 0);
#pragma unroll 4
        for (int j = 0; j < rem; j++) {
            int   s  = __shfl_sync(0xffffffffu, cw.x, j);
            float ww = __int_as_float(__shfl_sync(0xffffffffu, cw.y, j));
            uint2 r  = h2[(size_t)s * 32 + lane];
            float2 a0 = __half22float2(*reinterpret_cast<__half2*>(&r.x));
            float2 a1 = __half22float2(*reinterpret_cast<__half2*>(&r.y));
            acc.x += ww * a0.x; acc.y += ww * a0.y;
            acc.z += ww * a1.x; acc.w += ww * a1.y;
        }
    }

    float4 b = reinterpret_cast<const float4*>(bias)[lane];
    float4 o;
    o.x = fmaxf(acc.x + b.x, 0.f);
    o.y = fmaxf(acc.y + b.y, 0.f);
    o.z = fmaxf(acc.z + b.z, 0.f);
    o.w = fmaxf(acc.w + b.w, 0.f);
    out4[(size_t)node * 32 + lane] = o;
}

// ---------------- classifier: out[M,16] = h[M,128] @ Wc[128,16] + bc ------
__global__ void __launch_bounds__(256) classifier_kernel(
    const float* __restrict__ h, const float* __restrict__ Wc,
    const float* __restrict__ bc, float* __restrict__ out, int n)
{
    __shared__ float ws[128 * 16];
    __shared__ float hs[16][129];
    int tid = threadIdx.x;
    int row0 = blockIdx.x * 16;
#pragma unroll
    for (int p = 0; p < 8; p++) ws[p * 256 + tid] = Wc[p * 256 + tid];
#pragma unroll
    for (int p = 0; p < 8; p++) {
        int idx = p * 256 + tid;
        int r = idx >> 7, c = idx & 127;
        hs[r][c] = (row0 + r < n) ? h[(size_t)(row0 + r) * 128 + c] : 0.f;
    }
    __syncthreads();
    int r = tid >> 4, c = tid & 15;
    float acc = bc[c];
#pragma unroll 16
    for (int k = 0; k < 128; k++) acc = fmaf(hs[r][k], ws[k * 16 + c], acc);
    if (row0 + r < n) out[(size_t)(row0 + r) * 16 + c] = acc;
}

// ---------------- launch ----------------
extern "C" void kernel_launch(void* const* d_in, const int* in_sizes, int n_in,
                              void* d_out, int out_size)
{
    const float* x  = (const float*)d_in[0];
    const void*  ei = d_in[1];
    const float* W1 = (const float*)d_in[2];
    const float* b1 = (const float*)d_in[3];
    const float* W2 = (const float*)d_in[4];
    const float* b2 = (const float*)d_in[5];
    const float* Wc = (const float*)d_in[6];
    const float* bc = (const float*)d_in[7];
    float* out = (float*)d_out;

    int n = in_sizes[0] / 128;
    int e = in_sizes[1] / 2;

    __half* h;
    float*  a;
    cudaGetSymbolAddress((void**)&h, g_h);
    cudaGetSymbolAddress((void**)&a, g_a);

    int nb1024 = (n + 1023) / 1024;
    int nb256  = (n + 255) / 256;
    int ebk2   = ((e + 1) / 2 + 255) / 256;
    int gemmb  = (n + 63) / 64;

    init_kernel<<<nb256, 256>>>((const unsigned int*)ei, n);
    count_deg_kernel<<<ebk2, 256>>>(ei, e);
    scan_part_dinv_kernel<<<nb1024, 1024>>>(n);
    scan_top_kernel<<<1, 32>>>(nb1024);
    scan_final_kernel<<<nb1024, 1024>>>(n);

    // fat launch: gemm1 (independent of graph) + CSC build (needs rowptr)
    gemm1_build_kernel<<<gemmb + ebk2, 256>>>(x, W1, h, n, ei, e, gemmb);

    aggregate_kernel<<<(n + 7) / 8, 256>>>((const uint2*)h, b1, (float4*)a, n);
    gemm128_kernel<<<gemmb, 256>>>(a, W2, h, n);
    aggregate_kernel<<<(n + 7) / 8, 256>>>((const uint2*)h, b2, (float4*)a, n);
    classifier_kernel<<<(n + 15) / 16, 256>>>(a, Wc, bc, out, n);
}

// round 7
// speedup vs baseline: 2.4670x; 1.0068x over previous
#include <cuda_runtime.h>
#include <cuda_fp16.h>

// ---------------- problem-size constants ----------------
#define NMAX 50000
#define EMAX 1600000

// ---------------- scratch (device globals: no allocation allowed) --------
__device__ int   g_deg[NMAX];
__device__ float g_dinv[NMAX];
__device__ int   g_rowptr[NMAX + 1];
__device__ int   g_cursor[NMAX];
__device__ int2  g_cw[EMAX];                     // packed (src, w-bits)
__device__ __align__(16) __half g_h[(size_t)NMAX * 128];   // fp16 gather operand
__device__ __align__(16) float  g_a[(size_t)NMAX * 128];   // fp32 inter-layer
__device__ int g_bsum[64];
__device__ int g_boff[64];
__device__ int g_is64;   // 1 if edge_index is int64, 0 if int32

// ---------------- packed fp32x2 helpers (Blackwell FFMA2) ----------------
__device__ __forceinline__ unsigned long long pack2(float lo, float hi) {
    unsigned long long r;
    asm("mov.b64 %0, {%1, %2};"
        : "=l"(r) : "r"(__float_as_uint(lo)), "r"(__float_as_uint(hi)));
    return r;
}
__device__ __forceinline__ void unpack2(unsigned long long v, float &lo, float &hi) {
    unsigned int a, b;
    asm("mov.b64 {%0, %1}, %2;" : "=r"(a), "=r"(b) : "l"(v));
    lo = __uint_as_float(a);
    hi = __uint_as_float(b);
}
__device__ __forceinline__ void ffma2(unsigned long long &d,
                                      unsigned long long a,
                                      unsigned long long b) {
    asm("fma.rn.f32x2 %0, %1, %2, %0;" : "+l"(d) : "l"(a), "l"(b));
}

// ---------------- init: width detect (block 0) + zero degrees ------------
__global__ void init_kernel(const unsigned int* __restrict__ p, int n) {
    int i = blockIdx.x * blockDim.x + threadIdx.x;
    if (i < n) g_deg[i] = 0;
    if (blockIdx.x == 0) {
        __shared__ int any;
        if (threadIdx.x == 0) any = 0;
        __syncthreads();
        for (int k = threadIdx.x; k < 2048; k += blockDim.x) {
            if (p[2 * k + 1] != 0u) any = 1;
        }
        __syncthreads();
        if (threadIdx.x == 0) g_is64 = any ? 0 : 1;
    }
}

// dst-only degree count, 2 edges per thread (vectorized)
__global__ void count_deg_kernel(const void* __restrict__ ei, int e_total) {
    int t = blockIdx.x * blockDim.x + threadIdx.x;
    int base = t * 2;
    if (base >= e_total) return;
    int d0, d1;
    bool two = (base + 1 < e_total);
    if (g_is64) {
        const long long* p = (const long long*)ei + e_total;   // dst half
        if (two) {
            longlong2 v = *reinterpret_cast<const longlong2*>(p + base);
            d0 = (int)v.x; d1 = (int)v.y;
        } else { d0 = (int)p[base]; d1 = -1; }
    } else {
        const int* p = (const int*)ei + e_total;
        if (two) {
            int2 v = *reinterpret_cast<const int2*>(p + base);
            d0 = v.x; d1 = v.y;
        } else { d0 = p[base]; d1 = -1; }
    }
    atomicAdd(&g_deg[d0], 1);
    if (two) atomicAdd(&g_deg[d1], 1);
}

// ---------------- scan stage 1 (block sums) + dinv fused -----------------
__global__ void scan_part_dinv_kernel(int n) {
    __shared__ int sm[1024];
    int i = blockIdx.x * 1024 + threadIdx.x;
    int v = (i < n) ? g_deg[i] : 0;
    if (i < n) g_dinv[i] = rsqrtf((float)(v + 1));   // +1 self loop
    sm[threadIdx.x] = v;
    __syncthreads();
    for (int s = 512; s > 0; s >>= 1) {
        if (threadIdx.x < s) sm[threadIdx.x] += sm[threadIdx.x + s];
        __syncthreads();
    }
    if (threadIdx.x == 0) g_bsum[blockIdx.x] = sm[0];
}

// parallel exclusive scan of up to 64 block sums (one 64-thread block)
__global__ void scan_top_kernel(int nblocks) {
    __shared__ int sm[64];
    int t = threadIdx.x;
    int v = (t < nblocks) ? g_bsum[t] : 0;
    sm[t] = v;
    __syncthreads();
    for (int off = 1; off < 64; off <<= 1) {
        int add = (t >= off) ? sm[t - off] : 0;
        __syncthreads();
        sm[t] += add;
        __syncthreads();
    }
    if (t < nblocks) g_boff[t] = sm[t] - v;   // exclusive
}

__global__ void scan_final_kernel(int n) {
    __shared__ int sm[1024];
    int tid = threadIdx.x;
    int i = blockIdx.x * 1024 + tid;
    int v = (i < n) ? g_deg[i] : 0;
    sm[tid] = v;
    __syncthreads();
    for (int off = 1; off < 1024; off <<= 1) {
        int t = (tid >= off) ? sm[tid - off] : 0;
        __syncthreads();
        sm[tid] += t;
        __syncthreads();
    }
    if (i < n) {
        int start = g_boff[blockIdx.x] + sm[tid] - v;   // exclusive
        g_rowptr[i] = start;
        g_cursor[i] = start;
        if (i == n - 1) g_rowptr[n] = start + v;
    }
}

// ---------------- CSC build (dst-sorted edges), 2 edges per thread -------
__global__ void build_csr_kernel(const void* __restrict__ ei, int e_total) {
    int t = blockIdx.x * blockDim.x + threadIdx.x;
    int base = t * 2;
    if (base >= e_total) return;
    int s0, d0, s1 = 0, d1 = 0;
    bool two = (base + 1 < e_total);
    if (g_is64) {
        const long long* ps = (const long long*)ei;
        const long long* pd = ps + e_total;
        if (two) {
            longlong2 sv = *reinterpret_cast<const longlong2*>(ps + base);
            longlong2 dv = *reinterpret_cast<const longlong2*>(pd + base);
            s0 = (int)sv.x; s1 = (int)sv.y;
            d0 = (int)dv.x; d1 = (int)dv.y;
        } else { s0 = (int)ps[base]; d0 = (int)pd[base]; }
    } else {
        const int* ps = (const int*)ei;
        const int* pd = ps + e_total;
        if (two) {
            int2 sv = *reinterpret_cast<const int2*>(ps + base);
            int2 dv = *reinterpret_cast<const int2*>(pd + base);
            s0 = sv.x; s1 = sv.y;
            d0 = dv.x; d1 = dv.y;
        } else { s0 = ps[base]; d0 = pd[base]; }
    }
    {
        int pos = atomicAdd(&g_cursor[d0], 1);
        float w = g_dinv[s0] * g_dinv[d0];
        g_cw[pos] = make_int2(s0, __float_as_int(w));
    }
    if (two) {
        int pos = atomicAdd(&g_cursor[d1], 1);
        float w = g_dinv[s1] * g_dinv[d1];
        g_cw[pos] = make_int2(s1, __float_as_int(w));
    }
}

// ---------------- GEMM: C[M,128] = A[M,128] @ W[128,128] -> fp16 store ---
// Block: 64 rows x 128 cols, 256 threads, each thread 4 rows x 4 col-pairs.
__global__ void __launch_bounds__(256) gemm128_kernel(
    const float* __restrict__ A, const float* __restrict__ W,
    __half* __restrict__ C, int M)
{
    __shared__ unsigned long long xs[64][33];   // packed (v, v), padded
    __shared__ unsigned long long ws[32][64];   // packed (W[k][2cp], W[k][2cp+1])

    int tid  = threadIdx.x;
    int row0 = blockIdx.x * 64;
    int cpg  = tid & 15;        // col-pair group: cp = 16*j + cpg
    int rg   = tid >> 4;        // row group: rows rg*4 + i

    unsigned long long acc[4][4];
#pragma unroll
    for (int i = 0; i < 4; i++)
#pragma unroll
        for (int j = 0; j < 4; j++) acc[i][j] = 0ull;

    for (int kb = 0; kb < 128; kb += 32) {
        {
            int lr = tid >> 5;
            int lk = tid & 31;
#pragma unroll
            for (int p = 0; p < 8; p++) {
                int r = lr + p * 8;
                int grow = row0 + r;
                float v = (grow < M) ? A[(size_t)grow * 128 + kb + lk] : 0.f;
                xs[r][lk] = pack2(v, v);
            }
        }
        {
#pragma unroll
            for (int p = 0; p < 8; p++) {
                int idx = p * 256 + tid;
                int kk = idx >> 6;
                int cp = idx & 63;
                float2 wv = *reinterpret_cast<const float2*>(&W[(kb + kk) * 128 + cp * 2]);
                ws[kk][cp] = pack2(wv.x, wv.y);
            }
        }
        __syncthreads();

#pragma unroll
        for (int kk = 0; kk < 32; kk++) {
            unsigned long long wv[4], xv[4];
#pragma unroll
            for (int j = 0; j < 4; j++) wv[j] = ws[kk][16 * j + cpg];
#pragma unroll
            for (int i = 0; i < 4; i++) xv[i] = xs[rg * 4 + i][kk];
#pragma unroll
            for (int i = 0; i < 4; i++)
#pragma unroll
                for (int j = 0; j < 4; j++) ffma2(acc[i][j], xv[i], wv[j]);
        }
        __syncthreads();
    }

#pragma unroll
    for (int i = 0; i < 4; i++) {
        int grow = row0 + rg * 4 + i;
        if (grow < M) {
#pragma unroll
            for (int j = 0; j < 4; j++) {
                int cp = 16 * j + cpg;
                float lo, hi;
                unpack2(acc[i][j], lo, hi);
                *reinterpret_cast<__half2*>(&C[(size_t)grow * 128 + cp * 2]) =
                    __floats2half2_rn(lo, hi);
            }
        }
    }
}

// ---------------- aggregation: out = relu(bias + dinv^2*h[i] + sum w*h[src])
// One warp per node; lane handles 4 cols (8B fp16). fp32 accumulation.
__global__ void __launch_bounds__(256) aggregate_kernel(
    const uint2* __restrict__ h2, const float* __restrict__ bias,
    float4* __restrict__ out4, int n)
{
    int warp = (blockIdx.x * blockDim.x + threadIdx.x) >> 5;
    int lane = threadIdx.x & 31;
    if (warp >= n) return;
    int node = warp;

    float ds = g_dinv[node];
    float sw = ds * ds;                       // 1/deg (self-loop norm)
    uint2 raw = h2[(size_t)node * 32 + lane];
    float2 f0 = __half22float2(*reinterpret_cast<__half2*>(&raw.x));
    float2 f1 = __half22float2(*reinterpret_cast<__half2*>(&raw.y));
    float4 acc = make_float4(sw * f0.x, sw * f0.y, sw * f1.x, sw * f1.y);

    int e   = g_rowptr[node];
    int end = g_rowptr[node + 1];

    for (; e + 32 <= end; e += 32) {
        int2 cw = g_cw[e + lane];
#pragma unroll
        for (int j = 0; j < 32; j++) {
            int   s  = __shfl_sync(0xffffffffu, cw.x, j);
            float ww = __int_as_float(__shfl_sync(0xffffffffu, cw.y, j));
            uint2 r  = h2[(size_t)s * 32 + lane];
            float2 a0 = __half22float2(*reinterpret_cast<__half2*>(&r.x));
            float2 a1 = __half22float2(*reinterpret_cast<__half2*>(&r.y));
            acc.x += ww * a0.x; acc.y += ww * a0.y;
            acc.z += ww * a1.x; acc.w += ww * a1.y;
        }
    }
    if (e < end) {
        int rem = end - e;
        int2 cw = (lane < rem) ? g_cw[e + lane] : make_int2(0, 0);
#pragma unroll 4
        for (int j = 0; j < rem; j++) {
            int   s  = __shfl_sync(0xffffffffu, cw.x, j);
            float ww = __int_as_float(__shfl_sync(0xffffffffu, cw.y, j));
            uint2 r  = h2[(size_t)s * 32 + lane];
            float2 a0 = __half22float2(*reinterpret_cast<__half2*>(&r.x));
            float2 a1 = __half22float2(*reinterpret_cast<__half2*>(&r.y));
            acc.x += ww * a0.x; acc.y += ww * a0.y;
            acc.z += ww * a1.x; acc.w += ww * a1.y;
        }
    }

    float4 b = reinterpret_cast<const float4*>(bias)[lane];
    float4 o;
    o.x = fmaxf(acc.x + b.x, 0.f);
    o.y = fmaxf(acc.y + b.y, 0.f);
    o.z = fmaxf(acc.z + b.z, 0.f);
    o.w = fmaxf(acc.w + b.w, 0.f);
    out4[(size_t)node * 32 + lane] = o;
}

// ---------------- classifier: out[M,16] = h[M,128] @ Wc[128,16] + bc ------
__global__ void __launch_bounds__(256) classifier_kernel(
    const float* __restrict__ h, const float* __restrict__ Wc,
    const float* __restrict__ bc, float* __restrict__ out, int n)
{
    __shared__ float ws[128 * 16];
    __shared__ float hs[16][129];
    int tid = threadIdx.x;
    int row0 = blockIdx.x * 16;
#pragma unroll
    for (int p = 0; p < 8; p++) ws[p * 256 + tid] = Wc[p * 256 + tid];
#pragma unroll
    for (int p = 0; p < 8; p++) {
        int idx = p * 256 + tid;
        int r = idx >> 7, c = idx & 127;
        hs[r][c] = (row0 + r < n) ? h[(size_t)(row0 + r) * 128 + c] : 0.f;
    }
    __syncthreads();
    int r = tid >> 4, c = tid & 15;
    float acc = bc[c];
#pragma unroll 16
    for (int k = 0; k < 128; k++) acc = fmaf(hs[r][k], ws[k * 16 + c], acc);
    if (row0 + r < n) out[(size_t)(row0 + r) * 16 + c] = acc;
}

// ---------------- launch ----------------
extern "C" void kernel_launch(void* const* d_in, const int* in_sizes, int n_in,
                              void* d_out, int out_size)
{
    const float* x  = (const float*)d_in[0];
    const void*  ei = d_in[1];
    const float* W1 = (const float*)d_in[2];
    const float* b1 = (const float*)d_in[3];
    const float* W2 = (const float*)d_in[4];
    const float* b2 = (const float*)d_in[5];
    const float* Wc = (const float*)d_in[6];
    const float* bc = (const float*)d_in[7];
    float* out = (float*)d_out;

    int n = in_sizes[0] / 128;
    int e = in_sizes[1] / 2;

    __half* h;
    float*  a;
    cudaGetSymbolAddress((void**)&h, g_h);
    cudaGetSymbolAddress((void**)&a, g_a);

    int nb1024 = (n + 1023) / 1024;
    int nb256  = (n + 255) / 256;
    int ebk2   = ((e + 1) / 2 + 255) / 256;
    int gemmb  = (n + 63) / 64;

    // Lazy one-time creation of side stream + events (first call is the
    // uncaptured correctness run; capture calls only record/wait).
    static cudaStream_t s2 = nullptr;
    static cudaEvent_t ev_fork = nullptr, ev_join = nullptr;
    if (s2 == nullptr) {
        cudaStreamCreateWithFlags(&s2, cudaStreamNonBlocking);
        cudaEventCreateWithFlags(&ev_fork, cudaEventDisableTiming);
        cudaEventCreateWithFlags(&ev_join, cudaEventDisableTiming);
    }

    // Fork: gemm1 depends only on x/W1 — run it on the side stream,
    // overlapping the whole graph-preprocessing chain on the main stream.
    cudaEventRecord(ev_fork, 0);
    cudaStreamWaitEvent(s2, ev_fork, 0);
    gemm128_kernel<<<gemmb, 256, 0, s2>>>(x, W1, h, n);
    cudaEventRecord(ev_join, s2);

    // Main stream: preprocessing chain
    init_kernel<<<nb256, 256>>>((const unsigned int*)ei, n);
    count_deg_kernel<<<ebk2, 256>>>(ei, e);
    scan_part_dinv_kernel<<<nb1024, 1024>>>(n);
    scan_top_kernel<<<1, 64>>>(nb1024);
    scan_final_kernel<<<nb1024, 1024>>>(n);
    build_csr_kernel<<<ebk2, 256>>>(ei, e);

    // Join: aggregate1 needs both h (side stream) and g_cw (main stream).
    cudaStreamWaitEvent(0, ev_join, 0);

    aggregate_kernel<<<(n + 7) / 8, 256>>>((const uint2*)h, b1, (float4*)a, n);
    gemm128_kernel<<<gemmb, 256>>>(a, W2, h, n);
    aggregate_kernel<<<(n + 7) / 8, 256>>>((const uint2*)h, b2, (float4*)a, n);
    classifier_kernel<<<(n + 15) / 16, 256>>>(a, Wc, bc, out, n);
}

// round 8
// speedup vs baseline: 2.5145x; 1.0193x over previous
#include <cuda_runtime.h>
#include <cuda_fp16.h>

// ---------------- problem-size constants ----------------
#define NMAX 50000
#define EMAX 1600000

// ---------------- scratch (device globals: no allocation allowed) --------
__device__ int   g_deg[NMAX];          // zeroed at END of each run (build sect.)
__device__ float g_dinv[NMAX];
__device__ int   g_rowptr[NMAX + 1];
__device__ int   g_cursor[NMAX];
__device__ int2  g_cw[EMAX];                     // packed (src, w-bits)
__device__ __align__(16) __half g_h[(size_t)NMAX * 128];   // fp16 gather operand
__device__ __align__(16) float  g_a[(size_t)NMAX * 128];   // fp32 inter-layer
__device__ int g_bsum[64];
__device__ int g_is64;   // 1 if edge_index is int64, 0 if int32

// ---------------- packed fp32x2 helpers (Blackwell FFMA2) ----------------
__device__ __forceinline__ unsigned long long pack2(float lo, float hi) {
    unsigned long long r;
    asm("mov.b64 %0, {%1, %2};"
        : "=l"(r) : "r"(__float_as_uint(lo)), "r"(__float_as_uint(hi)));
    return r;
}
__device__ __forceinline__ void unpack2(unsigned long long v, float &lo, float &hi) {
    unsigned int a, b;
    asm("mov.b64 {%0, %1}, %2;" : "=r"(a), "=r"(b) : "l"(v));
    lo = __uint_as_float(a);
    hi = __uint_as_float(b);
}
__device__ __forceinline__ void ffma2(unsigned long long &d,
                                      unsigned long long a,
                                      unsigned long long b) {
    asm("fma.rn.f32x2 %0, %1, %2, %0;" : "+l"(d) : "l"(a), "l"(b));
}

// ---------------- width detection (tiny, 1 block) ----------------
__global__ void detect_kernel(const unsigned int* __restrict__ p) {
    __shared__ int any;
    if (threadIdx.x == 0) any = 0;
    __syncthreads();
    for (int k = threadIdx.x; k < 2048; k += blockDim.x) {
        if (p[2 * k + 1] != 0u) any = 1;
    }
    __syncthreads();
    if (threadIdx.x == 0) g_is64 = any ? 0 : 1;
}

// dst-only degree count, 2 edges per thread (vectorized).
// g_deg must be zero on entry (static init / re-zeroed by previous run).
__global__ void count_deg_kernel(const void* __restrict__ ei, int e_total) {
    int t = blockIdx.x * blockDim.x + threadIdx.x;
    int base = t * 2;
    if (base >= e_total) return;
    int d0, d1;
    bool two = (base + 1 < e_total);
    if (g_is64) {
        const long long* p = (const long long*)ei + e_total;   // dst half
        if (two) {
            longlong2 v = *reinterpret_cast<const longlong2*>(p + base);
            d0 = (int)v.x; d1 = (int)v.y;
        } else { d0 = (int)p[base]; d1 = -1; }
    } else {
        const int* p = (const int*)ei + e_total;
        if (two) {
            int2 v = *reinterpret_cast<const int2*>(p + base);
            d0 = v.x; d1 = v.y;
        } else { d0 = p[base]; d1 = -1; }
    }
    atomicAdd(&g_deg[d0], 1);
    if (two) atomicAdd(&g_deg[d1], 1);
}

// ---------------- scan stage 1 (block sums) + dinv fused -----------------
__global__ void scan_part_dinv_kernel(int n) {
    __shared__ int sm[1024];
    int i = blockIdx.x * 1024 + threadIdx.x;
    int v = (i < n) ? g_deg[i] : 0;
    if (i < n) g_dinv[i] = rsqrtf((float)(v + 1));   // +1 self loop
    sm[threadIdx.x] = v;
    __syncthreads();
    for (int s = 512; s > 0; s >>= 1) {
        if (threadIdx.x < s) sm[threadIdx.x] += sm[threadIdx.x + s];
        __syncthreads();
    }
    if (threadIdx.x == 0) g_bsum[blockIdx.x] = sm[0];
}

// ---------------- scan final (top-scan folded in-block) ------------------
__global__ void scan_final_kernel(int n, int nblocks) {
    __shared__ int sm[1024];
    __shared__ int topi[64];     // inclusive scan of block sums
    int tid = threadIdx.x;

    if (tid < 64) topi[tid] = (tid < nblocks) ? g_bsum[tid] : 0;
    __syncthreads();
    for (int off = 1; off < 64; off <<= 1) {
        int add = (tid < 64 && tid >= off) ? topi[tid - off] : 0;
        __syncthreads();
        if (tid < 64) topi[tid] += add;
        __syncthreads();
    }
    int boff = (blockIdx.x == 0) ? 0 : topi[blockIdx.x - 1];

    int i = blockIdx.x * 1024 + tid;
    int v = (i < n) ? g_deg[i] : 0;
    sm[tid] = v;
    __syncthreads();
    for (int off = 1; off < 1024; off <<= 1) {
        int t = (tid >= off) ? sm[tid - off] : 0;
        __syncthreads();
        sm[tid] += t;
        __syncthreads();
    }
    if (i < n) {
        int start = boff + sm[tid] - v;   // exclusive
        g_rowptr[i] = start;
        g_cursor[i] = start;
        if (i == n - 1) g_rowptr[n] = start + v;
    }
}

// ---------------- build body (CSC scatter + deg re-zero) -----------------
__device__ __forceinline__ void build_body(const void* __restrict__ ei,
                                           int e_total, int n, int t) {
    if (t < n) g_deg[t] = 0;     // re-zero for the NEXT run (nothing reads deg now)
    int base = t * 2;
    if (base >= e_total) return;
    int s0, d0, s1 = 0, d1 = 0;
    bool two = (base + 1 < e_total);
    if (g_is64) {
        const long long* ps = (const long long*)ei;
        const long long* pd = ps + e_total;
        if (two) {
            longlong2 sv = *reinterpret_cast<const longlong2*>(ps + base);
            longlong2 dv = *reinterpret_cast<const longlong2*>(pd + base);
            s0 = (int)sv.x; s1 = (int)sv.y;
            d0 = (int)dv.x; d1 = (int)dv.y;
        } else { s0 = (int)ps[base]; d0 = (int)pd[base]; }
    } else {
        const int* ps = (const int*)ei;
        const int* pd = ps + e_total;
        if (two) {
            int2 sv = *reinterpret_cast<const int2*>(ps + base);
            int2 dv = *reinterpret_cast<const int2*>(pd + base);
            s0 = sv.x; s1 = sv.y;
            d0 = dv.x; d1 = dv.y;
        } else { s0 = ps[base]; d0 = pd[base]; }
    }
    {
        int pos = atomicAdd(&g_cursor[d0], 1);
        float w = g_dinv[s0] * g_dinv[d0];
        g_cw[pos] = make_int2(s0, __float_as_int(w));
    }
    if (two) {
        int pos = atomicAdd(&g_cursor[d1], 1);
        float w = g_dinv[s1] * g_dinv[d1];
        g_cw[pos] = make_int2(s1, __float_as_int(w));
    }
}

// ---------------- GEMM block body: C[64,128] tile, packed f32x2 ----------
__device__ __forceinline__ void gemm_block_body(
    const float* __restrict__ A, const float* __restrict__ W,
    __half* __restrict__ C, int M, int blk,
    unsigned long long (*xs)[33], unsigned long long (*ws)[64])
{
    int tid  = threadIdx.x;
    int row0 = blk * 64;
    int cpg  = tid & 15;
    int rg   = tid >> 4;

    unsigned long long acc[4][4];
#pragma unroll
    for (int i = 0; i < 4; i++)
#pragma unroll
        for (int j = 0; j < 4; j++) acc[i][j] = 0ull;

    for (int kb = 0; kb < 128; kb += 32) {
        {
            int lr = tid >> 5;
            int lk = tid & 31;
#pragma unroll
            for (int p = 0; p < 8; p++) {
                int r = lr + p * 8;
                int grow = row0 + r;
                float v = (grow < M) ? A[(size_t)grow * 128 + kb + lk] : 0.f;
                xs[r][lk] = pack2(v, v);
            }
        }
        {
#pragma unroll
            for (int p = 0; p < 8; p++) {
                int idx = p * 256 + tid;
                int kk = idx >> 6;
                int cp = idx & 63;
                float2 wv = *reinterpret_cast<const float2*>(&W[(kb + kk) * 128 + cp * 2]);
                ws[kk][cp] = pack2(wv.x, wv.y);
            }
        }
        __syncthreads();

#pragma unroll
        for (int kk = 0; kk < 32; kk++) {
            unsigned long long wv[4], xv[4];
#pragma unroll
            for (int j = 0; j < 4; j++) wv[j] = ws[kk][16 * j + cpg];
#pragma unroll
            for (int i = 0; i < 4; i++) xv[i] = xs[rg * 4 + i][kk];
#pragma unroll
            for (int i = 0; i < 4; i++)
#pragma unroll
                for (int j = 0; j < 4; j++) ffma2(acc[i][j], xv[i], wv[j]);
        }
        __syncthreads();
    }

#pragma unroll
    for (int i = 0; i < 4; i++) {
        int grow = row0 + rg * 4 + i;
        if (grow < M) {
#pragma unroll
            for (int j = 0; j < 4; j++) {
                int cp = 16 * j + cpg;
                float lo, hi;
                unpack2(acc[i][j], lo, hi);
                *reinterpret_cast<__half2*>(&C[(size_t)grow * 128 + cp * 2]) =
                    __floats2half2_rn(lo, hi);
            }
        }
    }
}

// ---------------- standalone GEMM (layer 2) ----------------
__global__ void __launch_bounds__(256) gemm128_kernel(
    const float* __restrict__ A, const float* __restrict__ W,
    __half* __restrict__ C, int M)
{
    __shared__ unsigned long long xs[64][33];
    __shared__ unsigned long long ws[32][64];
    gemm_block_body(A, W, C, M, blockIdx.x, xs, ws);
}

// ---------------- fat kernel: gemm1 blocks + build blocks ----------------
__global__ void __launch_bounds__(256) gemm1_build_kernel(
    const float* __restrict__ A, const float* __restrict__ W,
    __half* __restrict__ C, int M,
    const void* __restrict__ ei, int e_total, int gemm_blocks)
{
    __shared__ unsigned long long xs[64][33];
    __shared__ unsigned long long ws[32][64];
    if (blockIdx.x < gemm_blocks) {
        gemm_block_body(A, W, C, M, blockIdx.x, xs, ws);
    } else {
        int t = (blockIdx.x - gemm_blocks) * blockDim.x + threadIdx.x;
        build_body(ei, e_total, M, t);
    }
}

// ---------------- aggregation (2 edges / iteration) ----------------------
// One warp per node. Lanes split in two 16-lane halves: half h processes
// edges 2j+h; lane (within half) l owns 8 cols via one LDG.128 of fp16.
// Partial accumulators folded by shfl_xor(16) at the end. fp32 accumulate.
__global__ void __launch_bounds__(256) aggregate_kernel(
    const uint4* __restrict__ h4, const float* __restrict__ bias,
    float4* __restrict__ out4, int n)
{
    int warp = (blockIdx.x * blockDim.x + threadIdx.x) >> 5;
    int lane = threadIdx.x & 31;
    if (warp >= n) return;
    int node = warp;
    int half = lane >> 4;
    int l    = lane & 15;

    float ds = g_dinv[node];
    float sw = (half == 0) ? ds * ds : 0.f;    // self term only on half 0

    float acc[8];
    {
        uint4 r = h4[(size_t)node * 16 + l];
        float2 p0 = __half22float2(*reinterpret_cast<const __half2*>(&r.x));
        float2 p1 = __half22float2(*reinterpret_cast<const __half2*>(&r.y));
        float2 p2 = __half22float2(*reinterpret_cast<const __half2*>(&r.z));
        float2 p3 = __half22float2(*reinterpret_cast<const __half2*>(&r.w));
        acc[0] = sw * p0.x; acc[1] = sw * p0.y;
        acc[2] = sw * p1.x; acc[3] = sw * p1.y;
        acc[4] = sw * p2.x; acc[5] = sw * p2.y;
        acc[6] = sw * p3.x; acc[7] = sw * p3.y;
    }

    int e   = g_rowptr[node];
    int end = g_rowptr[node + 1];

    // full 32-edge chunks, cw software-prefetched
    if (e + 32 <= end) {
        int2 cw = g_cw[e + lane];
        while (true) {
            int  e_next = e + 32;
            bool more   = (e_next + 32 <= end);
            int2 cw_next = make_int2(0, 0);
            if (more) cw_next = g_cw[e_next + lane];
#pragma unroll
            for (int j = 0; j < 16; j++) {
                int   idx = 2 * j + half;
                int   s   = __shfl_sync(0xffffffffu, cw.x, idx);
                float ww  = __int_as_float(__shfl_sync(0xffffffffu, cw.y, idx));
                uint4 r   = h4[(size_t)s * 16 + l];
                float2 p0 = __half22float2(*reinterpret_cast<const __half2*>(&r.x));
                float2 p1 = __half22float2(*reinterpret_cast<const __half2*>(&r.y));
                float2 p2 = __half22float2(*reinterpret_cast<const __half2*>(&r.z));
                float2 p3 = __half22float2(*reinterpret_cast<const __half2*>(&r.w));
                acc[0] += ww * p0.x; acc[1] += ww * p0.y;
                acc[2] += ww * p1.x; acc[3] += ww * p1.y;
                acc[4] += ww * p2.x; acc[5] += ww * p2.y;
                acc[6] += ww * p3.x; acc[7] += ww * p3.y;
            }
            e = e_next;
            if (!more) break;
            cw = cw_next;
        }
    }
    // tail: rem in [0, 32); zero-padded cw keeps all lanes converged
    int rem = end - e;
    if (rem > 0) {
        int2 cw = (lane < rem) ? g_cw[e + lane] : make_int2(0, 0);
        int jmax = (rem + 1) >> 1;
        for (int j = 0; j < jmax; j++) {
            int   idx = 2 * j + half;            // may exceed rem: cw there is 0
            int   s   = __shfl_sync(0xffffffffu, cw.x, idx);
            float ww  = __int_as_float(__shfl_sync(0xffffffffu, cw.y, idx));
            uint4 r   = h4[(size_t)s * 16 + l];
            float2 p0 = __half22float2(*reinterpret_cast<const __half2*>(&r.x));
            float2 p1 = __half22float2(*reinterpret_cast<const __half2*>(&r.y));
            float2 p2 = __half22float2(*reinterpret_cast<const __half2*>(&r.z));
            float2 p3 = __half22float2(*reinterpret_cast<const __half2*>(&r.w));
            acc[0] += ww * p0.x; acc[1] += ww * p0.y;
            acc[2] += ww * p1.x; acc[3] += ww * p1.y;
            acc[4] += ww * p2.x; acc[5] += ww * p2.y;
            acc[6] += ww * p3.x; acc[7] += ww * p3.y;
        }
    }

    // fold the two half-warp partials
#pragma unroll
    for (int k = 0; k < 8; k++)
        acc[k] += __shfl_xor_sync(0xffffffffu, acc[k], 16);

    if (half == 0) {
        float4 b0 = reinterpret_cast<const float4*>(bias)[l * 2];
        float4 b1 = reinterpret_cast<const float4*>(bias)[l * 2 + 1];
        float4 o0, o1;
        o0.x = fmaxf(acc[0] + b0.x, 0.f); o0.y = fmaxf(acc[1] + b0.y, 0.f);
        o0.z = fmaxf(acc[2] + b0.z, 0.f); o0.w = fmaxf(acc[3] + b0.w, 0.f);
        o1.x = fmaxf(acc[4] + b1.x, 0.f); o1.y = fmaxf(acc[5] + b1.y, 0.f);
        o1.z = fmaxf(acc[6] + b1.z, 0.f); o1.w = fmaxf(acc[7] + b1.w, 0.f);
        out4[(size_t)node * 32 + l * 2]     = o0;
        out4[(size_t)node * 32 + l * 2 + 1] = o1;
    }
}

// ---------------- classifier: out[M,16] = h[M,128] @ Wc[128,16] + bc ------
__global__ void __launch_bounds__(256) classifier_kernel(
    const float* __restrict__ h, const float* __restrict__ Wc,
    const float* __restrict__ bc, float* __restrict__ out, int n)
{
    __shared__ float ws[128 * 16];
    __shared__ float hs[16][129];
    int tid = threadIdx.x;
    int row0 = blockIdx.x * 16;
#pragma unroll
    for (int p = 0; p < 8; p++) ws[p * 256 + tid] = Wc[p * 256 + tid];
#pragma unroll
    for (int p = 0; p < 8; p++) {
        int idx = p * 256 + tid;
        int r = idx >> 7, c = idx & 127;
        hs[r][c] = (row0 + r < n) ? h[(size_t)(row0 + r) * 128 + c] : 0.f;
    }
    __syncthreads();
    int r = tid >> 4, c = tid & 15;
    float acc = bc[c];
#pragma unroll 16
    for (int k = 0; k < 128; k++) acc = fmaf(hs[r][k], ws[k * 16 + c], acc);
    if (row0 + r < n) out[(size_t)(row0 + r) * 16 + c] = acc;
}

// ---------------- launch ----------------
extern "C" void kernel_launch(void* const* d_in, const int* in_sizes, int n_in,
                              void* d_out, int out_size)
{
    const float* x  = (const float*)d_in[0];
    const void*  ei = d_in[1];
    const float* W1 = (const float*)d_in[2];
    const float* b1 = (const float*)d_in[3];
    const float* W2 = (const float*)d_in[4];
    const float* b2 = (const float*)d_in[5];
    const float* Wc = (const float*)d_in[6];
    const float* bc = (const float*)d_in[7];
    float* out = (float*)d_out;

    int n = in_sizes[0] / 128;
    int e = in_sizes[1] / 2;

    __half* h;
    float*  a;
    cudaGetSymbolAddress((void**)&h, g_h);
    cudaGetSymbolAddress((void**)&a, g_a);

    int nb1024 = (n + 1023) / 1024;
    int ebk2   = ((e + 1) / 2 + 255) / 256;
    int gemmb  = (n + 63) / 64;

    detect_kernel<<<1, 256>>>((const unsigned int*)ei);
    count_deg_kernel<<<ebk2, 256>>>(ei, e);
    scan_part_dinv_kernel<<<nb1024, 1024>>>(n);
    scan_final_kernel<<<nb1024, 1024>>>(n, nb1024);
    // fat launch: gemm1 (independent) + CSC build (+ deg re-zero for next run)
    gemm1_build_kernel<<<gemmb + ebk2, 256>>>(x, W1, h, n, ei, e, gemmb);

    aggregate_kernel<<<(n + 7) / 8, 256>>>((const uint4*)h, b1, (float4*)a, n);
    gemm128_kernel<<<gemmb, 256>>>(a, W2, h, n);
    aggregate_kernel<<<(n + 7) / 8, 256>>>((const uint4*)h, b2, (float4*)a, n);
    classifier_kernel<<<(n + 15) / 16, 256>>>(a, Wc, bc, out, n);
}